// round 1
// baseline (speedup 1.0000x reference)
#include <cuda_runtime.h>
#include <math.h>

#define D 128
#define L 512
#define Bb 128
#define BL (Bb*L)   // 65536 tokens
#define NBLK 2

// ---------------- scratch (device globals; no allocations allowed) ----------
__device__ float g_seqs [(size_t)BL*D];
__device__ float g_Q    [(size_t)BL*D];
__device__ float g_kbuf [(size_t)BL*D];
__device__ float g_vbuf [(size_t)BL*D];
__device__ float g_qp   [(size_t)BL*D];
__device__ float g_qproj[(size_t)BL*D];
__device__ float g_mha  [(size_t)BL*D];
__device__ float g_tmp  [(size_t)BL*D];
__device__ float g_attn [(size_t)BL*L];   // 134 MB
__device__ float g_E    [(size_t)BL*L];   // 134 MB
__device__ float g_cape [BL];

// ---------------- reduction helpers ----------------
__device__ __forceinline__ float warpSum(float v){
    #pragma unroll
    for (int o=16;o;o>>=1) v += __shfl_xor_sync(0xffffffffu, v, o);
    return v;
}
__device__ __forceinline__ float warpMax(float v){
    #pragma unroll
    for (int o=16;o;o>>=1) v = fmaxf(v, __shfl_xor_sync(0xffffffffu, v, o));
    return v;
}

// ---------------- embedding gather ----------------
__global__ void k_embed(const float* __restrict__ emb, const int* __restrict__ ids,
                        float* __restrict__ out, float scale){
    long long row = blockIdx.x;
    int d = threadIdx.x;
    long long idx = ids[row];
    out[row*D + d] = emb[idx*D + d] * scale;
}

// ---------------- layernorm (one token per 128-thread block) ----------------
__global__ void k_ln(const float* __restrict__ x, float* __restrict__ y,
                     const float* __restrict__ s, const float* __restrict__ b){
    long long row = blockIdx.x;
    int d = threadIdx.x;
    float v = x[row*D + d];
    __shared__ float red[4];
    int warp = d >> 5, lane = d & 31;
    float su = warpSum(v);
    if (lane==0) red[warp] = su;
    __syncthreads();
    float mean = ((red[0]+red[1])+(red[2]+red[3])) * (1.0f/D);
    __syncthreads();
    float c = v - mean;
    float sq = warpSum(c*c);
    if (lane==0) red[warp] = sq;
    __syncthreads();
    float var = ((red[0]+red[1])+(red[2]+red[3])) * (1.0f/D);
    y[row*D + d] = c * rsqrtf(var + 1e-8f) * s[d] + b[d];
}

// ---------------- generic tiled fp32 GEMM ----------------
// C[M,N] = act(alpha * A[M,K] @ op(B) + bias) + resid
//   transB=1 : B is [N,K] row-major (C = A @ B^T)   — weight matrices, QK^T
//   transB=0 : B is [K,N] row-major (C = A @ B)     — attn@V, qp@pos_emb
// batched over blockIdx.z with strides sA/sB/sC (resid uses sC).
#define BM 64
#define BN 64
#define BK 16
__global__ void k_gemm(const float* __restrict__ A, const float* __restrict__ Bm,
                       const float* __restrict__ bias, const float* __restrict__ resid,
                       float* __restrict__ C, int M, int N, int K,
                       long long sA, long long sB, long long sC,
                       float alpha, int transB, int act)
{
    A  += (long long)blockIdx.z * sA;
    Bm += (long long)blockIdx.z * sB;
    C  += (long long)blockIdx.z * sC;
    const float* R = resid ? (resid + (long long)blockIdx.z * sC) : (const float*)0;

    int bm = blockIdx.y * BM, bn = blockIdx.x * BN;
    __shared__ float As[BK][BM+1];
    __shared__ float Bs[BK][BN+1];
    int tid = threadIdx.x;          // 256 threads
    int tx = tid & 15, ty = tid >> 4;

    float acc[4][4];
    #pragma unroll
    for (int i=0;i<4;i++)
        #pragma unroll
        for (int j=0;j<4;j++) acc[i][j] = 0.0f;

    for (int k0 = 0; k0 < K; k0 += BK){
        #pragma unroll
        for (int it=0; it<(BM*BK)/256; it++){
            int idx = tid + it*256;
            int r = idx >> 4, c = idx & 15;
            As[c][r] = A[(long long)(bm + r)*K + k0 + c];
        }
        if (transB){
            #pragma unroll
            for (int it=0; it<(BN*BK)/256; it++){
                int idx = tid + it*256;
                int col = idx >> 4, c = idx & 15;
                Bs[c][col] = Bm[(long long)(bn + col)*K + k0 + c];
            }
        } else {
            #pragma unroll
            for (int it=0; it<(BN*BK)/256; it++){
                int idx = tid + it*256;
                int c = idx >> 6, col = idx & 63;
                Bs[c][col] = Bm[(long long)(k0 + c)*N + bn + col];
            }
        }
        __syncthreads();
        #pragma unroll
        for (int kk=0; kk<BK; kk++){
            float a[4], bb[4];
            #pragma unroll
            for (int i=0;i<4;i++) a[i] = As[kk][ty*4+i];
            #pragma unroll
            for (int j=0;j<4;j++) bb[j] = Bs[kk][tx*4+j];
            #pragma unroll
            for (int i=0;i<4;i++)
                #pragma unroll
                for (int j=0;j<4;j++) acc[i][j] = fmaf(a[i], bb[j], acc[i][j]);
        }
        __syncthreads();
    }

    #pragma unroll
    for (int i=0;i<4;i++){
        long long row = bm + ty*4 + i;
        #pragma unroll
        for (int j=0;j<4;j++){
            int col = bn + tx*4 + j;
            float v = acc[i][j] * alpha;
            if (bias) v += bias[col];
            if (act == 1) v = fmaxf(v, 0.0f);
            else if (act == 2) v = v / (1.0f + expf(-v));   // silu
            if (R) v += R[row*N + col];
            C[row*N + col] = v;
        }
    }
}

// ---------------- fused causal softmax + CAPE (one (b,q) row per block) -----
// In:  attn row = raw scaled scores; E row = qp @ pos_emb.
// Out: attn row = softmax probs (masked entries exactly 0), cape[row] = mean.
__global__ void k_softmax_cape(float* __restrict__ attn, const float* __restrict__ E,
                               float* __restrict__ cape){
    long long row = blockIdx.x;
    int qi = (int)(row & (L-1));
    int k = threadIdx.x;            // 512 threads
    __shared__ float sm[L];
    __shared__ float smE[L];
    __shared__ float red[16];
    int warp = k >> 5, lane = k & 31;

    float s = (k <= qi) ? attn[row*L + k] : -3.0e38f;
    // block max over valid entries
    float m = warpMax(s);
    if (lane==0) red[warp] = m;
    __syncthreads();
    if (warp==0){
        float t = (lane < 16) ? red[lane] : -3.0e38f;
        t = warpMax(t);
        if (lane==0) red[0] = t;
    }
    __syncthreads();
    m = red[0];
    __syncthreads();

    float e = (k <= qi) ? expf(s - m) : 0.0f;
    // block sum
    float z = warpSum(e);
    if (lane==0) red[warp] = z;
    __syncthreads();
    if (warp==0){
        float t = (lane < 16) ? red[lane] : 0.0f;
        t = warpSum(t);
        if (lane==0) red[0] = t;
    }
    __syncthreads();
    float Z = red[0];
    __syncthreads();

    float a = e / Z;                 // masked -> exactly 0 (matches jax: exp(-1e9-m) underflows)
    attn[row*L + k] = a;

    smE[k] = E[row*L + k];
    float G = 1.0f - 1.0f/(1.0f + expf(-a));   // masked: 1 - sigmoid(0) = 0.5 (matches ref)
    sm[k] = G;
    __syncthreads();

    // inclusive suffix scan (Hillis-Steele): P[k] = sum_{j>=k} G[j]
    #pragma unroll
    for (int off=1; off<L; off<<=1){
        float t = sm[k] + ((k+off < L) ? sm[k+off] : 0.0f);
        __syncthreads();
        sm[k] = t;
        __syncthreads();
    }

    float P = fminf(sm[k], (float)(L-1));
    float Pf = floorf(P);
    float frac = P - Pf;
    int i0 = (int)Pf;
    int i1 = (int)ceilf(P);
    float cv = frac * smE[i1] + (1.0f - frac) * smE[i0];

    float t2 = warpSum(cv);
    if (lane==0) red[warp] = t2;
    __syncthreads();
    if (warp==0){
        float t = (lane < 16) ? red[lane] : 0.0f;
        t = warpSum(t);
        if (lane==0) cape[row] = t * (1.0f/L);
    }
}

// ---------------- residual + broadcast cape ----------------
__global__ void k_add3(const float* __restrict__ a, const float* __restrict__ b,
                       const float* __restrict__ crow, float* __restrict__ out){
    long long row = blockIdx.x;
    int d = threadIdx.x;
    out[row*D + d] = a[row*D + d] + b[row*D + d] + crow[row];
}

// ---------------- final logits (pos then neg, concatenated) ----------------
__global__ void k_logits(const float* __restrict__ feats, const float* __restrict__ emb,
                         const int* __restrict__ pos, const int* __restrict__ neg,
                         float* __restrict__ out){
    long long row = blockIdx.x;
    int d = threadIdx.x;
    float f = feats[row*D + d];
    long long pi = pos[row], ni = neg[row];
    float pv = f * emb[pi*D + d];
    float nv = f * emb[ni*D + d];
    __shared__ float rp[4], rn[4];
    int warp = d >> 5, lane = d & 31;
    float sp = warpSum(pv), sn = warpSum(nv);
    if (lane==0){ rp[warp] = sp; rn[warp] = sn; }
    __syncthreads();
    if (d==0){
        out[row]            = (rp[0]+rp[1])+(rp[2]+rp[3]);
        out[(long long)BL + row] = (rn[0]+rn[1])+(rn[2]+rn[3]);
    }
}

// ---------------- host orchestration ----------------
extern "C" void kernel_launch(void* const* d_in, const int* in_sizes, int n_in,
                              void* d_out, int out_size)
{
    const float* item_emb = (const float*)d_in[0];
    const float* pos_emb  = (const float*)d_in[1];   // [D, MAXLEN] = [K,N] for E GEMM
    const float* pre_w    = (const float*)d_in[2];
    const float* pre_b    = (const float*)d_in[3];
    const float* ln1_s    = (const float*)d_in[4];
    const float* ln1_b    = (const float*)d_in[5];
    const float* in_w     = (const float*)d_in[6];
    const float* in_b     = (const float*)d_in[7];
    const float* out_w    = (const float*)d_in[8];
    const float* out_b    = (const float*)d_in[9];
    const float* ln2_s    = (const float*)d_in[10];
    const float* ln2_b    = (const float*)d_in[11];
    const float* c1_w     = (const float*)d_in[12];
    const float* c1_b     = (const float*)d_in[13];
    const float* c2_w     = (const float*)d_in[14];
    const float* c2_b     = (const float*)d_in[15];
    const float* lnf_s    = (const float*)d_in[16];
    const float* lnf_b    = (const float*)d_in[17];
    /* d_in[18] = user_ids (unused) */
    const int* log_seqs   = (const int*)d_in[19];
    const int* pos_seqs   = (const int*)d_in[20];
    const int* neg_seqs   = (const int*)d_in[21];
    float* out = (float*)d_out;

    float *seqs,*Q,*kb,*vb,*qp,*qpr,*mha,*tmp,*attn,*E,*cape;
    cudaGetSymbolAddress((void**)&seqs, g_seqs);
    cudaGetSymbolAddress((void**)&Q,    g_Q);
    cudaGetSymbolAddress((void**)&kb,   g_kbuf);
    cudaGetSymbolAddress((void**)&vb,   g_vbuf);
    cudaGetSymbolAddress((void**)&qp,   g_qp);
    cudaGetSymbolAddress((void**)&qpr,  g_qproj);
    cudaGetSymbolAddress((void**)&mha,  g_mha);
    cudaGetSymbolAddress((void**)&tmp,  g_tmp);
    cudaGetSymbolAddress((void**)&attn, g_attn);
    cudaGetSymbolAddress((void**)&E,    g_E);
    cudaGetSymbolAddress((void**)&cape, g_cape);

    const float inv_sqrt_d = 1.0f / sqrtf((float)D);

    k_embed<<<BL, D>>>(item_emb, log_seqs, seqs, sqrtf((float)D));

    dim3 gTok(D/BN, BL/BM, 1);     // token-wise DxD projections: (2, 1024)
    dim3 gScore(L/BN, L/BM, Bb);   // batched QK^T:               (8, 8, 128)
    dim3 gE(L/BN, BL/BM, 1);       // E = qp @ pos_emb:           (8, 1024)
    dim3 gMha(D/BN, L/BM, Bb);     // batched attn@V:             (2, 8, 128)

    for (int i = 0; i < NBLK; i++){
        const float* wq = in_w + (long long)i*3*D*D;
        const float* wk = wq + (long long)D*D;
        const float* wv = wk + (long long)D*D;
        const float* bq = in_b + (long long)i*3*D;

        // Q = LN1(seqs)
        k_ln<<<BL, D>>>(seqs, Q, ln1_s + i*D, ln1_b + i*D);
        // projections
        k_gemm<<<gTok, 256>>>(Q,    wq, bq,       0, qpr, BL, D, D, 0,0,0, 1.0f, 1, 0);
        k_gemm<<<gTok, 256>>>(seqs, wk, bq + D,   0, kb,  BL, D, D, 0,0,0, 1.0f, 1, 0);
        k_gemm<<<gTok, 256>>>(seqs, wv, bq + 2*D, 0, vb,  BL, D, D, 0,0,0, 1.0f, 1, 0);
        // qp = silu(Q @ pre_w^T + pre_b)
        k_gemm<<<gTok, 256>>>(Q, pre_w, pre_b, 0, qp, BL, D, D, 0,0,0, 1.0f, 1, 2);
        // scores = scale * q @ k^T  (batched over B)
        k_gemm<<<gScore, 256>>>(qpr, kb, 0, 0, attn, L, L, D,
                                (long long)L*D, (long long)L*D, (long long)L*L,
                                inv_sqrt_d, 1, 0);
        // E = qp @ pos_emb
        k_gemm<<<gE, 256>>>(qp, pos_emb, 0, 0, E, BL, L, D, 0,0,0, 1.0f, 0, 0);
        // softmax + CAPE per row
        k_softmax_cape<<<BL, L>>>(attn, E, cape);
        // mha_raw = attn @ v  (batched)
        k_gemm<<<gMha, 256>>>(attn, vb, 0, 0, mha, L, D, L,
                              (long long)L*L, (long long)L*D, (long long)L*D,
                              1.0f, 0, 0);
        // out proj
        k_gemm<<<gTok, 256>>>(mha, out_w + (long long)i*D*D, out_b + i*D, 0, tmp,
                              BL, D, D, 0,0,0, 1.0f, 1, 0);
        // seqs = Q + mha + cape_emb
        k_add3<<<BL, D>>>(Q, tmp, cape, seqs);
        // seqs = LN2(seqs)
        k_ln<<<BL, D>>>(seqs, seqs, ln2_s + i*D, ln2_b + i*D);
        // FFN: h = relu(seqs @ c1^T + b1); seqs = seqs + h @ c2^T + b2
        k_gemm<<<gTok, 256>>>(seqs, c1_w + (long long)i*D*D, c1_b + i*D, 0, tmp,
                              BL, D, D, 0,0,0, 1.0f, 1, 1);
        k_gemm<<<gTok, 256>>>(tmp, c2_w + (long long)i*D*D, c2_b + i*D, seqs, seqs,
                              BL, D, D, 0,0,0, 1.0f, 1, 0);
    }

    // feats = LN_f(seqs); logits
    k_ln<<<BL, D>>>(seqs, Q, lnf_s, lnf_b);
    k_logits<<<BL, D>>>(Q, item_emb, pos_seqs, neg_seqs, out);
}

// round 2
// speedup vs baseline: 2.1766x; 2.1766x over previous
#include <cuda_runtime.h>
#include <cuda_fp16.h>
#include <math.h>

#define D 128
#define L 512
#define Bb 128
#define BL (Bb*L)   // 65536 tokens
#define NBLK 2

// ---------------- scratch (device globals; no allocations allowed) ----------
__device__ float  g_seqs [(size_t)BL*D];
__device__ float  g_Q    [(size_t)BL*D];
__device__ float  g_mha  [(size_t)BL*D];
__device__ float  g_tmp  [(size_t)BL*D];
__device__ float  g_scores[(size_t)BL*L];      // 134 MB fp32 raw scores
__device__ float  g_cape [BL];
__device__ __half g_hq   [(size_t)BL*D];
__device__ __half g_hk   [(size_t)BL*D];
__device__ __half g_hv   [(size_t)BL*D];
__device__ __half g_hqp  [(size_t)BL*D];
__device__ __half g_hattn[(size_t)BL*L];       // 67 MB fp16 softmax probs
__device__ __half g_hE   [(size_t)BL*L];       // 67 MB fp16 CAPE logits
__device__ __half g_hpos [(size_t)D*L];

// ---------------- reduction helpers ----------------
__device__ __forceinline__ float warpSum(float v){
    #pragma unroll
    for (int o=16;o;o>>=1) v += __shfl_xor_sync(0xffffffffu, v, o);
    return v;
}
__device__ __forceinline__ float warpMax(float v){
    #pragma unroll
    for (int o=16;o;o>>=1) v = fmaxf(v, __shfl_xor_sync(0xffffffffu, v, o));
    return v;
}

// ---------------- embedding gather ----------------
__global__ void k_embed(const float* __restrict__ emb, const int* __restrict__ ids,
                        float* __restrict__ out, float scale){
    long long row = blockIdx.x;
    int d = threadIdx.x;
    long long idx = ids[row];
    out[row*D + d] = emb[idx*D + d] * scale;
}

__global__ void k_f2h(const float* __restrict__ x, __half* __restrict__ y, int n){
    int i = blockIdx.x*256 + threadIdx.x;
    if (i < n) y[i] = __float2half(x[i]);
}

// ---------------- layernorm (one token per 128-thread block) ----------------
__global__ void k_ln(const float* __restrict__ x, float* __restrict__ y,
                     const float* __restrict__ s, const float* __restrict__ b){
    long long row = blockIdx.x;
    int d = threadIdx.x;
    float v = x[row*D + d];
    __shared__ float red[4];
    int warp = d >> 5, lane = d & 31;
    float su = warpSum(v);
    if (lane==0) red[warp] = su;
    __syncthreads();
    float mean = ((red[0]+red[1])+(red[2]+red[3])) * (1.0f/D);
    __syncthreads();
    float c = v - mean;
    float sq = warpSum(c*c);
    if (lane==0) red[warp] = sq;
    __syncthreads();
    float var = ((red[0]+red[1])+(red[2]+red[3])) * (1.0f/D);
    y[row*D + d] = c * rsqrtf(var + 1e-8f) * s[d] + b[d];
}

// ---------------- fp32 token GEMM: C[M,128] = act(A[M,128] @ W^T + b) (+resid)
// W is [128,128] row-major ([N,K]).  8x8 microtile, 256 threads, BM=128.
// Output: fp32 (Cf) and/or fp16 (Ch).
__global__ void k_tokgemm(const float* __restrict__ A, const float* __restrict__ W,
                          const float* __restrict__ bias, const float* __restrict__ resid,
                          float* __restrict__ Cf, __half* __restrict__ Ch, int act)
{
    __shared__ float As[16][132];
    __shared__ float Ws[16][132];
    int tid = threadIdx.x;
    int tx = tid & 15, ty = tid >> 4;
    long long bm = (long long)blockIdx.x * 128;

    float acc[8][8];
    #pragma unroll
    for (int i=0;i<8;i++)
        #pragma unroll
        for (int j=0;j<8;j++) acc[i][j] = 0.0f;

    for (int k0 = 0; k0 < 128; k0 += 16){
        #pragma unroll
        for (int it=0; it<2; it++){
            int c = tid + it*256;
            int r = c >> 2, kc = c & 3;
            float4 va = *(const float4*)&A[(bm + r)*128 + k0 + kc*4];
            As[kc*4+0][r]=va.x; As[kc*4+1][r]=va.y; As[kc*4+2][r]=va.z; As[kc*4+3][r]=va.w;
            float4 vw = *(const float4*)&W[(long long)r*128 + k0 + kc*4];
            Ws[kc*4+0][r]=vw.x; Ws[kc*4+1][r]=vw.y; Ws[kc*4+2][r]=vw.z; Ws[kc*4+3][r]=vw.w;
        }
        __syncthreads();
        #pragma unroll
        for (int kk=0; kk<16; kk++){
            float4 a0 = *(const float4*)&As[kk][ty*8];
            float4 a1 = *(const float4*)&As[kk][ty*8+4];
            float4 b0 = *(const float4*)&Ws[kk][tx*8];
            float4 b1 = *(const float4*)&Ws[kk][tx*8+4];
            float a[8] = {a0.x,a0.y,a0.z,a0.w,a1.x,a1.y,a1.z,a1.w};
            float b[8] = {b0.x,b0.y,b0.z,b0.w,b1.x,b1.y,b1.z,b1.w};
            #pragma unroll
            for (int i=0;i<8;i++)
                #pragma unroll
                for (int j=0;j<8;j++) acc[i][j] = fmaf(a[i], b[j], acc[i][j]);
        }
        __syncthreads();
    }

    #pragma unroll
    for (int i=0;i<8;i++){
        long long row = bm + ty*8 + i;
        float v[8];
        #pragma unroll
        for (int j=0;j<8;j++){
            int col = tx*8 + j;
            float x = acc[i][j];
            if (bias) x += bias[col];
            if (act == 1) x = fmaxf(x, 0.0f);
            else if (act == 2) x = x / (1.0f + expf(-x));
            v[j] = x;
        }
        if (resid){
            float4 r0 = *(const float4*)&resid[row*128 + tx*8];
            float4 r1 = *(const float4*)&resid[row*128 + tx*8 + 4];
            v[0]+=r0.x; v[1]+=r0.y; v[2]+=r0.z; v[3]+=r0.w;
            v[4]+=r1.x; v[5]+=r1.y; v[6]+=r1.z; v[7]+=r1.w;
        }
        if (Cf){
            *(float4*)&Cf[row*128 + tx*8]     = make_float4(v[0],v[1],v[2],v[3]);
            *(float4*)&Cf[row*128 + tx*8 + 4] = make_float4(v[4],v[5],v[6],v[7]);
        }
        if (Ch){
            __half2* hp = (__half2*)&Ch[row*128 + tx*8];
            hp[0] = __floats2half2_rn(v[0],v[1]);
            hp[1] = __floats2half2_rn(v[2],v[3]);
            hp[2] = __floats2half2_rn(v[4],v[5]);
            hp[3] = __floats2half2_rn(v[6],v[7]);
        }
    }
}

// ---------------- fp16 tensor-core GEMM (mma.sync m16n8k16) -----------------
// C = alpha * A @ op(B).  A fp16 [M,K]; transB: B [N,K]; else B [K,N].
// causal=1: skip tiles fully above diagonal (scores).  causal=2: truncate K
// loop at the diagonal (attn@V, attn lower-triangular).  Batched via blockIdx.z.
#define HSK 40   // smem row stride (halfs)
__device__ __forceinline__ void mma16816(float* c, const unsigned* a, const unsigned* b){
    asm volatile(
        "mma.sync.aligned.m16n8k16.row.col.f32.f16.f16.f32 "
        "{%0,%1,%2,%3}, {%4,%5,%6,%7}, {%8,%9}, {%0,%1,%2,%3};\n"
        : "+f"(c[0]),"+f"(c[1]),"+f"(c[2]),"+f"(c[3])
        : "r"(a[0]),"r"(a[1]),"r"(a[2]),"r"(a[3]), "r"(b[0]),"r"(b[1]));
}
__global__ void k_hgemm(const __half* __restrict__ A, const __half* __restrict__ B,
                        float* __restrict__ Cf, __half* __restrict__ Ch,
                        int M, int N, int K,
                        long long sA, long long sB, long long sC,
                        float alpha, int transB, int causal)
{
    A += (long long)blockIdx.z * sA;
    B += (long long)blockIdx.z * sB;
    long long cOff = (long long)blockIdx.z * sC;
    int bm = blockIdx.y * 128, bn = blockIdx.x * 128;
    if (causal == 1 && bn >= bm + 128) return;
    int kend = (causal == 2) ? min(K, bm + 128) : K;

    __shared__ __half As[128][HSK];
    __shared__ __half Bs[128][HSK];
    int tid = threadIdx.x;
    int warp = tid >> 5, lane = tid & 31;
    int wm = (warp >> 2) * 64, wn = (warp & 3) * 32;
    int g = lane >> 2, tg = lane & 3;

    float acc[4][4][4];
    #pragma unroll
    for (int mi=0;mi<4;mi++)
        #pragma unroll
        for (int ni=0;ni<4;ni++)
            #pragma unroll
            for (int q=0;q<4;q++) acc[mi][ni][q] = 0.0f;

    for (int k0 = 0; k0 < kend; k0 += 32){
        #pragma unroll
        for (int it=0; it<2; it++){
            int c = tid + it*256;
            int r = c >> 2, q = c & 3;
            *(uint4*)&As[r][q*8] = *(const uint4*)&A[(long long)(bm+r)*K + k0 + q*8];
        }
        if (transB){
            #pragma unroll
            for (int it=0; it<2; it++){
                int c = tid + it*256;
                int r = c >> 2, q = c & 3;
                *(uint4*)&Bs[r][q*8] = *(const uint4*)&B[(long long)(bn+r)*K + k0 + q*8];
            }
        } else {
            #pragma unroll
            for (int it=0; it<2; it++){
                int c = tid + it*256;
                int kr = c >> 4, nq = c & 15;
                union { uint4 u; __half h[8]; } vv;
                vv.u = *(const uint4*)&B[(long long)(k0+kr)*N + bn + nq*8];
                #pragma unroll
                for (int j=0;j<8;j++) Bs[nq*8+j][kr] = vv.h[j];
            }
        }
        __syncthreads();
        #pragma unroll
        for (int kk=0; kk<32; kk+=16){
            unsigned af[4][4], bf[4][2];
            #pragma unroll
            for (int mi=0;mi<4;mi++){
                const __half* pa = &As[wm + mi*16 + g][kk + 2*tg];
                af[mi][0] = *(const unsigned*)pa;
                af[mi][1] = *(const unsigned*)(pa + 8*HSK);
                af[mi][2] = *(const unsigned*)(pa + 8);
                af[mi][3] = *(const unsigned*)(pa + 8*HSK + 8);
            }
            #pragma unroll
            for (int ni=0;ni<4;ni++){
                const __half* pb = &Bs[wn + ni*8 + g][kk + 2*tg];
                bf[ni][0] = *(const unsigned*)pb;
                bf[ni][1] = *(const unsigned*)(pb + 8);
            }
            #pragma unroll
            for (int mi=0;mi<4;mi++)
                #pragma unroll
                for (int ni=0;ni<4;ni++) mma16816(acc[mi][ni], af[mi], bf[ni]);
        }
        __syncthreads();
    }

    #pragma unroll
    for (int mi=0;mi<4;mi++){
        #pragma unroll
        for (int ni=0;ni<4;ni++){
            long long r0 = bm + wm + mi*16 + g;
            int c0 = bn + wn + ni*8 + 2*tg;
            float v0 = acc[mi][ni][0]*alpha, v1 = acc[mi][ni][1]*alpha;
            float v2 = acc[mi][ni][2]*alpha, v3 = acc[mi][ni][3]*alpha;
            if (Cf){
                *(float2*)&Cf[cOff + r0*N + c0]     = make_float2(v0, v1);
                *(float2*)&Cf[cOff + (r0+8)*N + c0] = make_float2(v2, v3);
            }
            if (Ch){
                *(__half2*)&Ch[cOff + r0*N + c0]     = __floats2half2_rn(v0, v1);
                *(__half2*)&Ch[cOff + (r0+8)*N + c0] = __floats2half2_rn(v2, v3);
            }
        }
    }
}

// ---------------- fused causal softmax + CAPE (one (b,q) row per block) -----
// In:  scores row (fp32 raw); hE row (fp16 CAPE logits).
// Out: hattn row (fp16 probs, masked = exact 0), cape[row] = mean of interp.
__global__ void k_softmax_cape(const float* __restrict__ scores, const __half* __restrict__ hE,
                               __half* __restrict__ hattn, float* __restrict__ cape){
    long long row = blockIdx.x;
    int qi = (int)(row & (L-1));
    int k = threadIdx.x;            // 512 threads, 16 warps
    __shared__ float smE[L];
    __shared__ float red[16];
    __shared__ float swarp[16];
    __shared__ float sexcl[16];
    int warp = k >> 5, lane = k & 31;

    smE[k] = __half2float(hE[row*L + k]);

    float s = (k <= qi) ? scores[row*L + k] : -3.0e38f;
    float m = warpMax(s);
    if (lane==0) red[warp] = m;
    __syncthreads();
    if (warp==0){
        float t = (lane < 16) ? red[lane] : -3.0e38f;
        t = warpMax(t);
        if (lane==0) red[0] = t;
    }
    __syncthreads();
    m = red[0];
    __syncthreads();

    float e = (k <= qi) ? expf(s - m) : 0.0f;
    float z = warpSum(e);
    if (lane==0) red[warp] = z;
    __syncthreads();
    if (warp==0){
        float t = (lane < 16) ? red[lane] : 0.0f;
        t = warpSum(t);
        if (lane==0) red[0] = t;
    }
    __syncthreads();
    float Z = red[0];

    float a = e / Z;                 // masked -> exactly 0
    hattn[row*L + k] = __float2half(a);

    // G = 1 - sigmoid(a); masked: 1 - sigmoid(0) = 0.5 (matches reference)
    float G = 1.0f - 1.0f/(1.0f + expf(-a));

    // intra-warp inclusive suffix scan
    float v = G;
    #pragma unroll
    for (int off=1; off<32; off<<=1){
        float t = __shfl_down_sync(0xffffffffu, v, off);
        if (lane + off < 32) v += t;
    }
    if (lane==0) swarp[warp] = v;     // warp total
    float vi = __shfl_sync(0xffffffffu, v, lane);  // keep own suffix (v already per-lane)
    __syncthreads();
    // warp 0: exclusive suffix over 16 warp totals
    if (warp==0 && lane<16){
        float x = swarp[lane];
        float inc = x;
        #pragma unroll
        for (int off=1; off<16; off<<=1){
            float t = __shfl_down_sync(0x0000ffffu, inc, off, 16);
            if (lane + off < 16) inc += t;
        }
        sexcl[lane] = inc - x;
    }
    __syncthreads();

    float P = vi + sexcl[warp];
    P = fminf(P, (float)(L-1));
    float Pf = floorf(P);
    float frac = P - Pf;
    int i0 = (int)Pf;
    int i1 = (int)ceilf(P);
    float cv = frac * smE[i1] + (1.0f - frac) * smE[i0];

    float t2 = warpSum(cv);
    if (lane==0) red[warp] = t2;
    __syncthreads();
    if (warp==0){
        float t = (lane < 16) ? red[lane] : 0.0f;
        t = warpSum(t);
        if (lane==0) cape[row] = t * (1.0f/L);
    }
}

// ---------------- residual + broadcast cape ----------------
__global__ void k_add3(const float* __restrict__ a, const float* __restrict__ b,
                       const float* __restrict__ crow, float* __restrict__ out){
    long long row = blockIdx.x;
    int d = threadIdx.x;
    out[row*D + d] = a[row*D + d] + b[row*D + d] + crow[row];
}

// ---------------- final logits (pos then neg, concatenated) ----------------
__global__ void k_logits(const float* __restrict__ feats, const float* __restrict__ emb,
                         const int* __restrict__ pos, const int* __restrict__ neg,
                         float* __restrict__ out){
    long long row = blockIdx.x;
    int d = threadIdx.x;
    float f = feats[row*D + d];
    long long pi = pos[row], ni = neg[row];
    float pv = f * emb[pi*D + d];
    float nv = f * emb[ni*D + d];
    __shared__ float rp[4], rn[4];
    int warp = d >> 5, lane = d & 31;
    float sp = warpSum(pv), sn = warpSum(nv);
    if (lane==0){ rp[warp] = sp; rn[warp] = sn; }
    __syncthreads();
    if (d==0){
        out[row]                 = (rp[0]+rp[1])+(rp[2]+rp[3]);
        out[(long long)BL + row] = (rn[0]+rn[1])+(rn[2]+rn[3]);
    }
}

// ---------------- host orchestration ----------------
extern "C" void kernel_launch(void* const* d_in, const int* in_sizes, int n_in,
                              void* d_out, int out_size)
{
    const float* item_emb = (const float*)d_in[0];
    const float* pos_emb  = (const float*)d_in[1];   // [D, MAXLEN]
    const float* pre_w    = (const float*)d_in[2];
    const float* pre_b    = (const float*)d_in[3];
    const float* ln1_s    = (const float*)d_in[4];
    const float* ln1_b    = (const float*)d_in[5];
    const float* in_w     = (const float*)d_in[6];
    const float* in_b     = (const float*)d_in[7];
    const float* out_w    = (const float*)d_in[8];
    const float* out_b    = (const float*)d_in[9];
    const float* ln2_s    = (const float*)d_in[10];
    const float* ln2_b    = (const float*)d_in[11];
    const float* c1_w     = (const float*)d_in[12];
    const float* c1_b     = (const float*)d_in[13];
    const float* c2_w     = (const float*)d_in[14];
    const float* c2_b     = (const float*)d_in[15];
    const float* lnf_s    = (const float*)d_in[16];
    const float* lnf_b    = (const float*)d_in[17];
    /* d_in[18] = user_ids (unused) */
    const int* log_seqs   = (const int*)d_in[19];
    const int* pos_seqs   = (const int*)d_in[20];
    const int* neg_seqs   = (const int*)d_in[21];
    float* out = (float*)d_out;

    float *seqs,*Q,*mha,*tmp,*scores,*cape;
    __half *hq,*hk,*hv,*hqp,*hattn,*hE,*hpos;
    cudaGetSymbolAddress((void**)&seqs,  g_seqs);
    cudaGetSymbolAddress((void**)&Q,     g_Q);
    cudaGetSymbolAddress((void**)&mha,   g_mha);
    cudaGetSymbolAddress((void**)&tmp,   g_tmp);
    cudaGetSymbolAddress((void**)&scores,g_scores);
    cudaGetSymbolAddress((void**)&cape,  g_cape);
    cudaGetSymbolAddress((void**)&hq,    g_hq);
    cudaGetSymbolAddress((void**)&hk,    g_hk);
    cudaGetSymbolAddress((void**)&hv,    g_hv);
    cudaGetSymbolAddress((void**)&hqp,   g_hqp);
    cudaGetSymbolAddress((void**)&hattn, g_hattn);
    cudaGetSymbolAddress((void**)&hE,    g_hE);
    cudaGetSymbolAddress((void**)&hpos,  g_hpos);

    const float inv_sqrt_d = 1.0f / sqrtf((float)D);

    k_embed<<<BL, D>>>(item_emb, log_seqs, seqs, sqrtf((float)D));
    k_f2h<<<(D*L+255)/256, 256>>>(pos_emb, hpos, D*L);

    dim3 gTok(BL/128, 1, 1);       // 512 blocks
    dim3 gScore(L/128, L/128, Bb); // (4,4,128), ~40% early-exit
    dim3 gE(L/128, BL/128, 1);     // (4,512)
    dim3 gMha(D/128, L/128, Bb);   // (1,4,128)

    for (int i = 0; i < NBLK; i++){
        const float* wq = in_w + (long long)i*3*D*D;
        const float* wk = wq + (long long)D*D;
        const float* wv = wk + (long long)D*D;
        const float* bq = in_b + (long long)i*3*D;

        // Q = LN1(seqs)
        k_ln<<<BL, D>>>(seqs, Q, ln1_s + i*D, ln1_b + i*D);
        // projections (fp32 compute, fp16 outputs where only attention consumes)
        k_tokgemm<<<gTok, 256>>>(Q,    wq,    bq,       0, 0, hq,  0);
        k_tokgemm<<<gTok, 256>>>(seqs, wk,    bq + D,   0, 0, hk,  0);
        k_tokgemm<<<gTok, 256>>>(seqs, wv,    bq + 2*D, 0, 0, hv,  0);
        k_tokgemm<<<gTok, 256>>>(Q,    pre_w, pre_b,    0, 0, hqp, 2);  // silu
        // scores = scale * q @ k^T (tensor cores, causal-skipped, batched)
        k_hgemm<<<gScore, 256>>>(hq, hk, scores, 0, L, L, D,
                                 (long long)L*D, (long long)L*D, (long long)L*L,
                                 inv_sqrt_d, 1, 1);
        // E = qp @ pos_emb (tensor cores) -> fp16
        k_hgemm<<<gE, 256>>>(hqp, hpos, 0, hE, BL, L, D,
                             0, 0, 0, 1.0f, 0, 0);
        // softmax + CAPE per row -> fp16 attn + cape scalar
        k_softmax_cape<<<BL, L>>>(scores, hE, hattn, cape);
        // mha_raw = attn @ v (tensor cores, K truncated at diagonal, batched)
        k_hgemm<<<gMha, 256>>>(hattn, hv, mha, 0, L, D, L,
                               (long long)L*L, (long long)L*D, (long long)L*D,
                               1.0f, 0, 2);
        // out proj (fp32)
        k_tokgemm<<<gTok, 256>>>(mha, out_w + (long long)i*D*D, out_b + i*D, 0, tmp, 0, 0);
        // seqs = Q + mha + cape_emb
        k_add3<<<BL, D>>>(Q, tmp, cape, seqs);
        // seqs = LN2(seqs)
        k_ln<<<BL, D>>>(seqs, seqs, ln2_s + i*D, ln2_b + i*D);
        // FFN (fp32): h = relu(seqs @ c1^T + b1); seqs = seqs + h @ c2^T + b2
        k_tokgemm<<<gTok, 256>>>(seqs, c1_w + (long long)i*D*D, c1_b + i*D, 0,    tmp,  0, 1);
        k_tokgemm<<<gTok, 256>>>(tmp,  c2_w + (long long)i*D*D, c2_b + i*D, seqs, seqs, 0, 0);
    }

    // feats = LN_f(seqs); logits
    k_ln<<<BL, D>>>(seqs, Q, lnf_s, lnf_b);
    k_logits<<<BL, D>>>(Q, item_emb, pos_seqs, neg_seqs, out);
}

// round 3
// speedup vs baseline: 3.9939x; 1.8349x over previous
#include <cuda_runtime.h>
#include <cuda_fp16.h>
#include <math.h>

#define D 128
#define L 512
#define Bb 128
#define BL (Bb*L)   // 65536 tokens
#define NBLK 2

// ---------------- scratch (device globals; no allocations allowed) ----------
__device__ float  g_seqs [(size_t)BL*D];
__device__ float  g_Q    [(size_t)BL*D];
__device__ float  g_mha  [(size_t)BL*D];
__device__ float  g_tmp  [(size_t)BL*D];
__device__ float  g_cape [BL];
__device__ __half g_hq   [(size_t)BL*D];
__device__ __half g_hk   [(size_t)BL*D];
__device__ __half g_hv   [(size_t)BL*D];
__device__ __half g_hqp  [(size_t)BL*D];
__device__ __half g_hscores[(size_t)BL*L];     // 67 MB fp16 raw scores
__device__ __half g_hattn[(size_t)BL*L];       // 67 MB fp16 softmax probs
__device__ __half g_hE   [(size_t)BL*L];       // 67 MB fp16 CAPE logits
__device__ __half g_hpos [(size_t)D*L];

// ---------------- reduction helpers ----------------
__device__ __forceinline__ float warpSum(float v){
    #pragma unroll
    for (int o=16;o;o>>=1) v += __shfl_xor_sync(0xffffffffu, v, o);
    return v;
}
__device__ __forceinline__ float warpMax(float v){
    #pragma unroll
    for (int o=16;o;o>>=1) v = fmaxf(v, __shfl_xor_sync(0xffffffffu, v, o));
    return v;
}

// ---------------- embedding gather ----------------
__global__ void k_embed(const float* __restrict__ emb, const int* __restrict__ ids,
                        float* __restrict__ out, float scale){
    long long row = blockIdx.x;
    int d = threadIdx.x;
    long long idx = ids[row];
    out[row*D + d] = emb[idx*D + d] * scale;
}

__global__ void k_f2h(const float* __restrict__ x, __half* __restrict__ y, int n){
    int i = blockIdx.x*256 + threadIdx.x;
    if (i < n) y[i] = __float2half(x[i]);
}

// ---------------- layernorm (one token per 128-thread block) ----------------
__global__ void k_ln(const float* __restrict__ x, float* __restrict__ y,
                     const float* __restrict__ s, const float* __restrict__ b){
    long long row = blockIdx.x;
    int d = threadIdx.x;
    float v = x[row*D + d];
    __shared__ float red[4];
    int warp = d >> 5, lane = d & 31;
    float su = warpSum(v);
    if (lane==0) red[warp] = su;
    __syncthreads();
    float mean = ((red[0]+red[1])+(red[2]+red[3])) * (1.0f/D);
    __syncthreads();
    float c = v - mean;
    float sq = warpSum(c*c);
    if (lane==0) red[warp] = sq;
    __syncthreads();
    float var = ((red[0]+red[1])+(red[2]+red[3])) * (1.0f/D);
    y[row*D + d] = c * rsqrtf(var + 1e-8f) * s[d] + b[d];
}

// ---------------- fused (Q + mha + cape) -> LN2 ----------------
__global__ void k_add3ln(const float* __restrict__ a, const float* __restrict__ b,
                         const float* __restrict__ crow, float* __restrict__ out,
                         const float* __restrict__ s, const float* __restrict__ bb){
    long long row = blockIdx.x;
    int d = threadIdx.x;
    float v = a[row*D + d] + b[row*D + d] + crow[row];
    __shared__ float red[4];
    int warp = d >> 5, lane = d & 31;
    float su = warpSum(v);
    if (lane==0) red[warp] = su;
    __syncthreads();
    float mean = ((red[0]+red[1])+(red[2]+red[3])) * (1.0f/D);
    __syncthreads();
    float c = v - mean;
    float sq = warpSum(c*c);
    if (lane==0) red[warp] = sq;
    __syncthreads();
    float var = ((red[0]+red[1])+(red[2]+red[3])) * (1.0f/D);
    out[row*D + d] = c * rsqrtf(var + 1e-8f) * s[d] + bb[d];
}

// ---------------- fused final LN + logits ----------------
__global__ void k_lnlogits(const float* __restrict__ x, const float* __restrict__ s,
                           const float* __restrict__ b, const float* __restrict__ emb,
                           const int* __restrict__ pos, const int* __restrict__ neg,
                           float* __restrict__ out){
    long long row = blockIdx.x;
    int d = threadIdx.x;
    float v = x[row*D + d];
    __shared__ float red[4], rp[4], rn[4];
    int warp = d >> 5, lane = d & 31;
    float su = warpSum(v);
    if (lane==0) red[warp] = su;
    __syncthreads();
    float mean = ((red[0]+red[1])+(red[2]+red[3])) * (1.0f/D);
    __syncthreads();
    float c = v - mean;
    float sq = warpSum(c*c);
    if (lane==0) red[warp] = sq;
    __syncthreads();
    float var = ((red[0]+red[1])+(red[2]+red[3])) * (1.0f/D);
    float f = c * rsqrtf(var + 1e-8f) * s[d] + b[d];
    long long pi = pos[row], ni = neg[row];
    float sp = warpSum(f * emb[pi*D + d]);
    float sn = warpSum(f * emb[ni*D + d]);
    if (lane==0){ rp[warp] = sp; rn[warp] = sn; }
    __syncthreads();
    if (d==0){
        out[row]                 = (rp[0]+rp[1])+(rp[2]+rp[3]);
        out[(long long)BL + row] = (rn[0]+rn[1])+(rn[2]+rn[3]);
    }
}

// ---------------- tensor-core token GEMM -------------------------------------
// C[M,128] = act(A[M,128]@W^T + b) (+resid).  A,W fp32 in gmem, converted to
// fp16 at smem load; fp32 MMA accumulation; outputs fp32 (Cf) and/or fp16 (Ch).
#define TSK 40
__device__ __forceinline__ void mma16816(float* c, const unsigned* a, const unsigned* b){
    asm volatile(
        "mma.sync.aligned.m16n8k16.row.col.f32.f16.f16.f32 "
        "{%0,%1,%2,%3}, {%4,%5,%6,%7}, {%8,%9}, {%0,%1,%2,%3};\n"
        : "+f"(c[0]),"+f"(c[1]),"+f"(c[2]),"+f"(c[3])
        : "r"(a[0]),"r"(a[1]),"r"(a[2]),"r"(a[3]), "r"(b[0]),"r"(b[1]));
}
__global__ void k_tokgemm_tc(const float* __restrict__ A, const float* __restrict__ W,
                             const float* __restrict__ bias, const float* __restrict__ resid,
                             float* __restrict__ Cf, __half* __restrict__ Ch, int act)
{
    __shared__ __half As[128][TSK];
    __shared__ __half Ws[128][TSK];
    int tid = threadIdx.x;
    int warp = tid >> 5, lane = tid & 31;
    int wm = (warp >> 2) * 64, wn = (warp & 3) * 32;
    int g = lane >> 2, tg = lane & 3;
    long long bm = (long long)blockIdx.x * 128;

    float acc[4][4][4];
    #pragma unroll
    for (int mi=0;mi<4;mi++)
        #pragma unroll
        for (int ni=0;ni<4;ni++)
            #pragma unroll
            for (int q=0;q<4;q++) acc[mi][ni][q] = 0.0f;

    for (int k0 = 0; k0 < 128; k0 += 32){
        // 128 rows x 32 cols per buffer = 1024 float4 chunks / 256 thr = 4 iters
        #pragma unroll
        for (int it=0; it<4; it++){
            int idx = tid + it*256;
            int r = idx >> 3, c4 = idx & 7;
            float4 va = *(const float4*)&A[(bm + r)*128 + k0 + c4*4];
            __half2* pa = (__half2*)&As[r][c4*4];
            pa[0] = __floats2half2_rn(va.x, va.y);
            pa[1] = __floats2half2_rn(va.z, va.w);
            float4 vw = *(const float4*)&W[(long long)r*128 + k0 + c4*4];
            __half2* pw = (__half2*)&Ws[r][c4*4];
            pw[0] = __floats2half2_rn(vw.x, vw.y);
            pw[1] = __floats2half2_rn(vw.z, vw.w);
        }
        __syncthreads();
        #pragma unroll
        for (int kk=0; kk<32; kk+=16){
            unsigned af[4][4], bf[4][2];
            #pragma unroll
            for (int mi=0;mi<4;mi++){
                const __half* pa = &As[wm + mi*16 + g][kk + 2*tg];
                af[mi][0] = *(const unsigned*)pa;
                af[mi][1] = *(const unsigned*)(pa + 8*TSK);
                af[mi][2] = *(const unsigned*)(pa + 8);
                af[mi][3] = *(const unsigned*)(pa + 8*TSK + 8);
            }
            #pragma unroll
            for (int ni=0;ni<4;ni++){
                const __half* pb = &Ws[wn + ni*8 + g][kk + 2*tg];
                bf[ni][0] = *(const unsigned*)pb;
                bf[ni][1] = *(const unsigned*)(pb + 8);
            }
            #pragma unroll
            for (int mi=0;mi<4;mi++)
                #pragma unroll
                for (int ni=0;ni<4;ni++) mma16816(acc[mi][ni], af[mi], bf[ni]);
        }
        __syncthreads();
    }

    #pragma unroll
    for (int mi=0;mi<4;mi++){
        #pragma unroll
        for (int ni=0;ni<4;ni++){
            long long r0 = bm + wm + mi*16 + g;
            int c0 = wn + ni*8 + 2*tg;
            float v[4] = {acc[mi][ni][0], acc[mi][ni][1], acc[mi][ni][2], acc[mi][ni][3]};
            if (bias){
                float b0 = bias[c0], b1 = bias[c0+1];
                v[0]+=b0; v[1]+=b1; v[2]+=b0; v[3]+=b1;
            }
            if (act == 1){
                #pragma unroll
                for (int q=0;q<4;q++) v[q] = fmaxf(v[q], 0.0f);
            } else if (act == 2){
                #pragma unroll
                for (int q=0;q<4;q++) v[q] = v[q] / (1.0f + expf(-v[q]));
            }
            if (resid){
                float2 r0v = *(const float2*)&resid[r0*128 + c0];
                float2 r1v = *(const float2*)&resid[(r0+8)*128 + c0];
                v[0]+=r0v.x; v[1]+=r0v.y; v[2]+=r1v.x; v[3]+=r1v.y;
            }
            if (Cf){
                *(float2*)&Cf[r0*128 + c0]     = make_float2(v[0], v[1]);
                *(float2*)&Cf[(r0+8)*128 + c0] = make_float2(v[2], v[3]);
            }
            if (Ch){
                *(__half2*)&Ch[r0*128 + c0]     = __floats2half2_rn(v[0], v[1]);
                *(__half2*)&Ch[(r0+8)*128 + c0] = __floats2half2_rn(v[2], v[3]);
            }
        }
    }
}

// ---------------- fp16 tensor-core GEMM (mma.sync m16n8k16) -----------------
#define HSK 40
__global__ void k_hgemm(const __half* __restrict__ A, const __half* __restrict__ B,
                        float* __restrict__ Cf, __half* __restrict__ Ch,
                        int M, int N, int K,
                        long long sA, long long sB, long long sC,
                        float alpha, int transB, int causal)
{
    A += (long long)blockIdx.z * sA;
    B += (long long)blockIdx.z * sB;
    long long cOff = (long long)blockIdx.z * sC;
    int bm = blockIdx.y * 128, bn = blockIdx.x * 128;
    if (causal == 1 && bn >= bm + 128) return;
    int kend = (causal == 2) ? min(K, bm + 128) : K;

    __shared__ __half As[128][HSK];
    __shared__ __half Bs[128][HSK];
    int tid = threadIdx.x;
    int warp = tid >> 5, lane = tid & 31;
    int wm = (warp >> 2) * 64, wn = (warp & 3) * 32;
    int g = lane >> 2, tg = lane & 3;

    float acc[4][4][4];
    #pragma unroll
    for (int mi=0;mi<4;mi++)
        #pragma unroll
        for (int ni=0;ni<4;ni++)
            #pragma unroll
            for (int q=0;q<4;q++) acc[mi][ni][q] = 0.0f;

    for (int k0 = 0; k0 < kend; k0 += 32){
        #pragma unroll
        for (int it=0; it<2; it++){
            int c = tid + it*256;
            int r = c >> 2, q = c & 3;
            *(uint4*)&As[r][q*8] = *(const uint4*)&A[(long long)(bm+r)*K + k0 + q*8];
        }
        if (transB){
            #pragma unroll
            for (int it=0; it<2; it++){
                int c = tid + it*256;
                int r = c >> 2, q = c & 3;
                *(uint4*)&Bs[r][q*8] = *(const uint4*)&B[(long long)(bn+r)*K + k0 + q*8];
            }
        } else {
            #pragma unroll
            for (int it=0; it<2; it++){
                int c = tid + it*256;
                int kr = c >> 4, nq = c & 15;
                union { uint4 u; __half h[8]; } vv;
                vv.u = *(const uint4*)&B[(long long)(k0+kr)*N + bn + nq*8];
                #pragma unroll
                for (int j=0;j<8;j++) Bs[nq*8+j][kr] = vv.h[j];
            }
        }
        __syncthreads();
        #pragma unroll
        for (int kk=0; kk<32; kk+=16){
            unsigned af[4][4], bf[4][2];
            #pragma unroll
            for (int mi=0;mi<4;mi++){
                const __half* pa = &As[wm + mi*16 + g][kk + 2*tg];
                af[mi][0] = *(const unsigned*)pa;
                af[mi][1] = *(const unsigned*)(pa + 8*HSK);
                af[mi][2] = *(const unsigned*)(pa + 8);
                af[mi][3] = *(const unsigned*)(pa + 8*HSK + 8);
            }
            #pragma unroll
            for (int ni=0;ni<4;ni++){
                const __half* pb = &Bs[wn + ni*8 + g][kk + 2*tg];
                bf[ni][0] = *(const unsigned*)pb;
                bf[ni][1] = *(const unsigned*)(pb + 8);
            }
            #pragma unroll
            for (int mi=0;mi<4;mi++)
                #pragma unroll
                for (int ni=0;ni<4;ni++) mma16816(acc[mi][ni], af[mi], bf[ni]);
        }
        __syncthreads();
    }

    #pragma unroll
    for (int mi=0;mi<4;mi++){
        #pragma unroll
        for (int ni=0;ni<4;ni++){
            long long r0 = bm + wm + mi*16 + g;
            int c0 = bn + wn + ni*8 + 2*tg;
            float v0 = acc[mi][ni][0]*alpha, v1 = acc[mi][ni][1]*alpha;
            float v2 = acc[mi][ni][2]*alpha, v3 = acc[mi][ni][3]*alpha;
            if (Cf){
                *(float2*)&Cf[cOff + r0*N + c0]     = make_float2(v0, v1);
                *(float2*)&Cf[cOff + (r0+8)*N + c0] = make_float2(v2, v3);
            }
            if (Ch){
                *(__half2*)&Ch[cOff + r0*N + c0]     = __floats2half2_rn(v0, v1);
                *(__half2*)&Ch[cOff + (r0+8)*N + c0] = __floats2half2_rn(v2, v3);
            }
        }
    }
}

// ---------------- fused causal softmax + CAPE, one warp per row -------------
// 256 threads = 8 warps = 8 rows per block.  No block-level barriers.
__global__ void k_softmax_cape(const __half* __restrict__ scores, const __half* __restrict__ hE,
                               __half* __restrict__ hattn, float* __restrict__ cape){
    int warp = threadIdx.x >> 5, lane = threadIdx.x & 31;
    long long row = (long long)blockIdx.x * 8 + warp;
    int qi = (int)(row & (L-1));
    __shared__ float smE[8][L];

    // load E row into this warp's smem slice (coalesced)
    const __half* Erow = hE + row*L;
    #pragma unroll
    for (int j=0;j<16;j++) smE[warp][lane + 32*j] = __half2float(Erow[lane + 32*j]);
    __syncwarp();

    // load 16 contiguous scores per lane
    const __half* Srow = scores + row*L;
    __half hs[16];
    *(uint4*)&hs[0] = *(const uint4*)&Srow[lane*16];
    *(uint4*)&hs[8] = *(const uint4*)&Srow[lane*16 + 8];

    float s[16];
    int base = lane*16;
    #pragma unroll
    for (int j=0;j<16;j++) s[j] = (base + j <= qi) ? __half2float(hs[j]) : -3.0e38f;

    float m = -3.0e38f;
    #pragma unroll
    for (int j=0;j<16;j++) m = fmaxf(m, s[j]);
    m = warpMax(m);

    float e[16], zs = 0.0f;
    #pragma unroll
    for (int j=0;j<16;j++){ e[j] = (base + j <= qi) ? expf(s[j] - m) : 0.0f; zs += e[j]; }
    float Z = warpSum(zs);
    float invZ = 1.0f / Z;

    __half ha[16];
    float G[16];
    #pragma unroll
    for (int j=0;j<16;j++){
        float a = e[j] * invZ;
        ha[j] = __float2half(a);
        G[j] = 1.0f - 1.0f/(1.0f + expf(-a));   // masked: 0.5 (matches reference)
    }
    __half* Arow = hattn + row*L;
    *(uint4*)&Arow[lane*16]     = *(const uint4*)&ha[0];
    *(uint4*)&Arow[lane*16 + 8] = *(const uint4*)&ha[8];

    // suffix scan: local (within 16) then across lanes
    float S[16];
    S[15] = G[15];
    #pragma unroll
    for (int j=14;j>=0;j--) S[j] = S[j+1] + G[j];
    float total = S[0];
    float inc = total;
    #pragma unroll
    for (int off=1; off<32; off<<=1){
        float t = __shfl_down_sync(0xffffffffu, inc, off);
        if (lane + off < 32) inc += t;
    }
    float excl = inc - total;   // sum of totals of lanes > lane

    float cv = 0.0f;
    #pragma unroll
    for (int j=0;j<16;j++){
        float P = fminf(S[j] + excl, (float)(L-1));
        float Pf = floorf(P);
        float frac = P - Pf;
        int i0 = (int)Pf;
        int i1 = (int)ceilf(P);
        cv += frac * smE[warp][i1] + (1.0f - frac) * smE[warp][i0];
    }
    float t2 = warpSum(cv);
    if (lane==0) cape[row] = t2 * (1.0f/L);
}

// ---------------- host orchestration ----------------
extern "C" void kernel_launch(void* const* d_in, const int* in_sizes, int n_in,
                              void* d_out, int out_size)
{
    const float* item_emb = (const float*)d_in[0];
    const float* pos_emb  = (const float*)d_in[1];   // [D, MAXLEN]
    const float* pre_w    = (const float*)d_in[2];
    const float* pre_b    = (const float*)d_in[3];
    const float* ln1_s    = (const float*)d_in[4];
    const float* ln1_b    = (const float*)d_in[5];
    const float* in_w     = (const float*)d_in[6];
    const float* in_b     = (const float*)d_in[7];
    const float* out_w    = (const float*)d_in[8];
    const float* out_b    = (const float*)d_in[9];
    const float* ln2_s    = (const float*)d_in[10];
    const float* ln2_b    = (const float*)d_in[11];
    const float* c1_w     = (const float*)d_in[12];
    const float* c1_b     = (const float*)d_in[13];
    const float* c2_w     = (const float*)d_in[14];
    const float* c2_b     = (const float*)d_in[15];
    const float* lnf_s    = (const float*)d_in[16];
    const float* lnf_b    = (const float*)d_in[17];
    /* d_in[18] = user_ids (unused) */
    const int* log_seqs   = (const int*)d_in[19];
    const int* pos_seqs   = (const int*)d_in[20];
    const int* neg_seqs   = (const int*)d_in[21];
    float* out = (float*)d_out;

    float *seqs,*Q,*mha,*tmp,*cape;
    __half *hq,*hk,*hv,*hqp,*hscores,*hattn,*hE,*hpos;
    cudaGetSymbolAddress((void**)&seqs,   g_seqs);
    cudaGetSymbolAddress((void**)&Q,      g_Q);
    cudaGetSymbolAddress((void**)&mha,    g_mha);
    cudaGetSymbolAddress((void**)&tmp,    g_tmp);
    cudaGetSymbolAddress((void**)&cape,   g_cape);
    cudaGetSymbolAddress((void**)&hq,     g_hq);
    cudaGetSymbolAddress((void**)&hk,     g_hk);
    cudaGetSymbolAddress((void**)&hv,     g_hv);
    cudaGetSymbolAddress((void**)&hqp,    g_hqp);
    cudaGetSymbolAddress((void**)&hscores,g_hscores);
    cudaGetSymbolAddress((void**)&hattn,  g_hattn);
    cudaGetSymbolAddress((void**)&hE,     g_hE);
    cudaGetSymbolAddress((void**)&hpos,   g_hpos);

    const float inv_sqrt_d = 1.0f / sqrtf((float)D);

    k_embed<<<BL, D>>>(item_emb, log_seqs, seqs, sqrtf((float)D));
    k_f2h<<<(D*L+255)/256, 256>>>(pos_emb, hpos, D*L);

    dim3 gTok(BL/128, 1, 1);       // 512 blocks
    dim3 gScore(L/128, L/128, Bb); // (4,4,128), ~40% early-exit
    dim3 gE(L/128, BL/128, 1);     // (4,512)
    dim3 gMha(D/128, L/128, Bb);   // (1,4,128)

    for (int i = 0; i < NBLK; i++){
        const float* wq = in_w + (long long)i*3*D*D;
        const float* wk = wq + (long long)D*D;
        const float* wv = wk + (long long)D*D;
        const float* bq = in_b + (long long)i*3*D;

        // Q = LN1(seqs)
        k_ln<<<BL, D>>>(seqs, Q, ln1_s + i*D, ln1_b + i*D);
        // projections (tensor cores, fp16 outputs)
        k_tokgemm_tc<<<gTok, 256>>>(Q,    wq,    bq,       0, 0, hq,  0);
        k_tokgemm_tc<<<gTok, 256>>>(seqs, wk,    bq + D,   0, 0, hk,  0);
        k_tokgemm_tc<<<gTok, 256>>>(seqs, wv,    bq + 2*D, 0, 0, hv,  0);
        k_tokgemm_tc<<<gTok, 256>>>(Q,    pre_w, pre_b,    0, 0, hqp, 2);  // silu
        // scores = scale * q @ k^T (TC, causal-skipped, batched) -> fp16
        k_hgemm<<<gScore, 256>>>(hq, hk, 0, hscores, L, L, D,
                                 (long long)L*D, (long long)L*D, (long long)L*L,
                                 inv_sqrt_d, 1, 1);
        // E = qp @ pos_emb (TC) -> fp16
        k_hgemm<<<gE, 256>>>(hqp, hpos, 0, hE, BL, L, D,
                             0, 0, 0, 1.0f, 0, 0);
        // softmax + CAPE, warp per row
        k_softmax_cape<<<BL/8, 256>>>(hscores, hE, hattn, cape);
        // mha_raw = attn @ v (TC, K truncated at diagonal, batched)
        k_hgemm<<<gMha, 256>>>(hattn, hv, mha, 0, L, D, L,
                               (long long)L*L, (long long)L*D, (long long)L*D,
                               1.0f, 0, 2);
        // out proj (TC, fp32 out)
        k_tokgemm_tc<<<gTok, 256>>>(mha, out_w + (long long)i*D*D, out_b + i*D, 0, tmp, 0, 0);
        // seqs = LN2(Q + mha + cape)
        k_add3ln<<<BL, D>>>(Q, tmp, cape, seqs, ln2_s + i*D, ln2_b + i*D);
        // FFN (TC): h = relu(seqs @ c1^T + b1); seqs = seqs + h @ c2^T + b2
        k_tokgemm_tc<<<gTok, 256>>>(seqs, c1_w + (long long)i*D*D, c1_b + i*D, 0,    tmp,  0, 1);
        k_tokgemm_tc<<<gTok, 256>>>(tmp,  c2_w + (long long)i*D*D, c2_b + i*D, seqs, seqs, 0, 0);
    }

    // feats = LN_f(seqs); logits (fused)
    k_lnlogits<<<BL, D>>>(seqs, lnf_s, lnf_b, item_emb, pos_seqs, neg_seqs, out);
}

// round 4
// speedup vs baseline: 4.5563x; 1.1408x over previous
#include <cuda_runtime.h>
#include <cuda_fp16.h>
#include <math.h>

#define D 128
#define L 512
#define Bb 128
#define BL (Bb*L)   // 65536 tokens
#define NBLK 2
#define ASTR 136                      // smem row stride in halfs
#define TILE_B (128*ASTR*2)           // 34816 bytes per fp16 tile

// ---------------- scratch (device globals; no allocations allowed) ----------
__device__ float  g_seqs [(size_t)BL*D];
__device__ float  g_Q    [(size_t)BL*D];
__device__ float  g_s2   [(size_t)BL*D];
__device__ float  g_cape [BL];
__device__ __half g_hseqs[(size_t)BL*D];
__device__ __half g_hQ   [(size_t)BL*D];
__device__ __half g_hs2  [(size_t)BL*D];
__device__ __half g_hq   [(size_t)BL*D];
__device__ __half g_hk   [(size_t)BL*D];
__device__ __half g_hv   [(size_t)BL*D];
__device__ __half g_hqp  [(size_t)BL*D];
__device__ __half g_hmha [(size_t)BL*D];
__device__ __half g_hscores[(size_t)BL*L];
__device__ __half g_hattn[(size_t)BL*L];
__device__ __half g_hE   [(size_t)BL*L];
__device__ __half g_hpos [(size_t)D*L];

// ---------------- helpers ----------------
__device__ __forceinline__ float warpSum(float v){
    #pragma unroll
    for (int o=16;o;o>>=1) v += __shfl_xor_sync(0xffffffffu, v, o);
    return v;
}
__device__ __forceinline__ float warpMax(float v){
    #pragma unroll
    for (int o=16;o;o>>=1) v = fmaxf(v, __shfl_xor_sync(0xffffffffu, v, o));
    return v;
}
__device__ __forceinline__ void mma16816(float* c, const unsigned* a, const unsigned* b){
    asm volatile(
        "mma.sync.aligned.m16n8k16.row.col.f32.f16.f16.f32 "
        "{%0,%1,%2,%3}, {%4,%5,%6,%7}, {%8,%9}, {%0,%1,%2,%3};\n"
        : "+f"(c[0]),"+f"(c[1]),"+f"(c[2]),"+f"(c[3])
        : "r"(a[0]),"r"(a[1]),"r"(a[2]),"r"(a[3]), "r"(b[0]),"r"(b[1]));
}
// load A-fragments for 64 M-rows x 16 K from smem tile (stride ASTR)
__device__ __forceinline__ void loadA(unsigned af[4][4], const __half* As, int wm, int g, int tg, int kk){
    #pragma unroll
    for (int mi=0;mi<4;mi++){
        const __half* pa = &As[(wm + mi*16 + g)*ASTR + kk + 2*tg];
        af[mi][0] = *(const unsigned*)pa;
        af[mi][1] = *(const unsigned*)(pa + 8*ASTR);
        af[mi][2] = *(const unsigned*)(pa + 8);
        af[mi][3] = *(const unsigned*)(pa + 8*ASTR + 8);
    }
}
__device__ __forceinline__ void loadB(unsigned bf[4][2], const __half* Bs, int wn, int g, int tg, int kk){
    #pragma unroll
    for (int ni=0;ni<4;ni++){
        const __half* pb = &Bs[(wn + ni*8 + g)*ASTR + kk + 2*tg];
        bf[ni][0] = *(const unsigned*)pb;
        bf[ni][1] = *(const unsigned*)(pb + 8);
    }
}

// ---------------- embedding gather (warp per token) ----------------
__global__ void k_embed(const float* __restrict__ emb, const int* __restrict__ ids,
                        float* __restrict__ out, __half* __restrict__ hout, float scale){
    int warp = threadIdx.x >> 5, lane = threadIdx.x & 31;
    long long row = (long long)blockIdx.x * 8 + warp;
    long long idx = ids[row];
    float4 v = *(const float4*)&emb[idx*D + lane*4];
    v.x*=scale; v.y*=scale; v.z*=scale; v.w*=scale;
    *(float4*)&out[row*D + lane*4] = v;
    __half2* hp = (__half2*)&hout[row*D + lane*4];
    hp[0] = __floats2half2_rn(v.x, v.y);
    hp[1] = __floats2half2_rn(v.z, v.w);
}

__global__ void k_f2h(const float* __restrict__ x, __half* __restrict__ y, int n){
    int i = blockIdx.x*256 + threadIdx.x;
    if (i < n) y[i] = __float2half(x[i]);
}

// ---------------- layernorm, warp per token, dual output ----------------
__global__ void k_ln_dual(const float* __restrict__ x, float* __restrict__ y,
                          __half* __restrict__ hy,
                          const float* __restrict__ s, const float* __restrict__ b){
    int warp = threadIdx.x >> 5, lane = threadIdx.x & 31;
    long long row = (long long)blockIdx.x * 8 + warp;
    float4 v = *(const float4*)&x[row*D + lane*4];
    float mean = warpSum(v.x+v.y+v.z+v.w) * (1.0f/D);
    float cx=v.x-mean, cy=v.y-mean, cz=v.z-mean, cw=v.w-mean;
    float var = warpSum(cx*cx+cy*cy+cz*cz+cw*cw) * (1.0f/D);
    float rstd = rsqrtf(var + 1e-8f);
    float4 sv = *(const float4*)&s[lane*4];
    float4 bv = *(const float4*)&b[lane*4];
    float o0 = cx*rstd*sv.x+bv.x, o1 = cy*rstd*sv.y+bv.y;
    float o2 = cz*rstd*sv.z+bv.z, o3 = cw*rstd*sv.w+bv.w;
    *(float4*)&y[row*D + lane*4] = make_float4(o0,o1,o2,o3);
    __half2* hp = (__half2*)&hy[row*D + lane*4];
    hp[0] = __floats2half2_rn(o0,o1);
    hp[1] = __floats2half2_rn(o2,o3);
}

// ---------------- fused final LN + logits ----------------
__global__ void k_lnlogits(const float* __restrict__ x, const float* __restrict__ s,
                           const float* __restrict__ b, const float* __restrict__ emb,
                           const int* __restrict__ pos, const int* __restrict__ neg,
                           float* __restrict__ out){
    long long row = blockIdx.x;
    int d = threadIdx.x;
    float v = x[row*D + d];
    __shared__ float red[4], rp[4], rn[4];
    int warp = d >> 5, lane = d & 31;
    float su = warpSum(v);
    if (lane==0) red[warp] = su;
    __syncthreads();
    float mean = ((red[0]+red[1])+(red[2]+red[3])) * (1.0f/D);
    __syncthreads();
    float c = v - mean;
    float sq = warpSum(c*c);
    if (lane==0) red[warp] = sq;
    __syncthreads();
    float var = ((red[0]+red[1])+(red[2]+red[3])) * (1.0f/D);
    float f = c * rsqrtf(var + 1e-8f) * s[d] + b[d];
    long long pi = pos[row], ni = neg[row];
    float sp = warpSum(f * emb[pi*D + d]);
    float sn = warpSum(f * emb[ni*D + d]);
    if (lane==0){ rp[warp] = sp; rn[warp] = sn; }
    __syncthreads();
    if (d==0){
        out[row]                 = (rp[0]+rp[1])+(rp[2]+rp[3]);
        out[(long long)BL + row] = (rn[0]+rn[1])+(rn[2]+rn[3]);
    }
}

// ---------------- fused QKV + pre_proj (4 weights, A tiles smem-resident) ---
__global__ void k_qkvp(const __half* __restrict__ hQ, const __half* __restrict__ hS,
                       const float* __restrict__ w0, const float* __restrict__ w1,
                       const float* __restrict__ w2, const float* __restrict__ w3,
                       const float* __restrict__ b012, const float* __restrict__ b3,
                       __half* __restrict__ o0, __half* __restrict__ o1,
                       __half* __restrict__ o2, __half* __restrict__ o3)
{
    extern __shared__ __half sm[];
    __half* AsQ = sm;
    __half* AsS = sm + 128*ASTR;
    __half* Ws  = sm + 2*128*ASTR;
    int tid = threadIdx.x;
    int warp = tid >> 5, lane = tid & 31;
    int wm = (warp >> 2) * 64, wn = (warp & 3) * 32;
    int g = lane >> 2, tg = lane & 3;
    long long bm = (long long)blockIdx.x * 128;

    // A tiles: 128 rows x 16 uint4 = 2048 chunks
    #pragma unroll
    for (int it=0; it<8; it++){
        int idx = tid + it*256;
        int r = idx >> 4, c = idx & 15;
        *(uint4*)&AsQ[r*ASTR + c*8] = *(const uint4*)&hQ[(bm+r)*128 + c*8];
        *(uint4*)&AsS[r*ASTR + c*8] = *(const uint4*)&hS[(bm+r)*128 + c*8];
    }
    const float* Wp[4] = {w0, w1, w2, w3};
    __half* Op[4] = {o0, o1, o2, o3};

    for (int w=0; w<4; w++){
        // weight fp32 -> fp16 smem: 128x32 float4 chunks
        #pragma unroll
        for (int it=0; it<16; it++){
            int idx = tid + it*256;
            int r = idx >> 5, c4 = idx & 31;
            float4 vw = *(const float4*)&Wp[w][(long long)r*128 + c4*4];
            __half2* pw = (__half2*)&Ws[r*ASTR + c4*4];
            pw[0] = __floats2half2_rn(vw.x, vw.y);
            pw[1] = __floats2half2_rn(vw.z, vw.w);
        }
        __syncthreads();
        const __half* As = (w==0 || w==3) ? AsQ : AsS;
        float acc[4][4][4];
        #pragma unroll
        for (int mi=0;mi<4;mi++)
            #pragma unroll
            for (int ni=0;ni<4;ni++)
                #pragma unroll
                for (int q=0;q<4;q++) acc[mi][ni][q] = 0.0f;
        #pragma unroll
        for (int kk=0; kk<128; kk+=16){
            unsigned af[4][4], bf[4][2];
            loadA(af, As, wm, g, tg, kk);
            loadB(bf, Ws, wn, g, tg, kk);
            #pragma unroll
            for (int mi=0;mi<4;mi++)
                #pragma unroll
                for (int ni=0;ni<4;ni++) mma16816(acc[mi][ni], af[mi], bf[ni]);
        }
        const float* bias = (w < 3) ? (b012 + w*128) : b3;
        __half* out = Op[w];
        #pragma unroll
        for (int mi=0;mi<4;mi++){
            #pragma unroll
            for (int ni=0;ni<4;ni++){
                long long r0 = bm + wm + mi*16 + g;
                int c0 = wn + ni*8 + 2*tg;
                float b0 = bias[c0], b1 = bias[c0+1];
                float v0 = acc[mi][ni][0]+b0, v1 = acc[mi][ni][1]+b1;
                float v2 = acc[mi][ni][2]+b0, v3 = acc[mi][ni][3]+b1;
                if (w == 3){
                    v0 = __fdividef(v0, 1.0f + __expf(-v0));
                    v1 = __fdividef(v1, 1.0f + __expf(-v1));
                    v2 = __fdividef(v2, 1.0f + __expf(-v2));
                    v3 = __fdividef(v3, 1.0f + __expf(-v3));
                }
                *(__half2*)&out[r0*128 + c0]     = __floats2half2_rn(v0, v1);
                *(__half2*)&out[(r0+8)*128 + c0] = __floats2half2_rn(v2, v3);
            }
        }
        __syncthreads();
    }
}

// ---------------- full-K(=128)-resident fp16 GEMM ----------------
// C = alpha * A[M,128] @ op(B).  transB=1: B[N,128]; else B[128,N].
// causal=1: skip tiles fully above diagonal.
__global__ void k_hgemm128(const __half* __restrict__ A, const __half* __restrict__ B,
                           float* __restrict__ Cf, __half* __restrict__ Ch, int N,
                           long long sA, long long sB, long long sC,
                           float alpha, int transB, int causal)
{
    A += (long long)blockIdx.z * sA;
    B += (long long)blockIdx.z * sB;
    long long cOff = (long long)blockIdx.z * sC;
    int bm = blockIdx.y * 128, bn = blockIdx.x * 128;
    if (causal && bn >= bm + 128) return;

    extern __shared__ __half sm[];
    __half* As = sm;
    __half* Bs = sm + 128*ASTR;
    int tid = threadIdx.x;
    int warp = tid >> 5, lane = tid & 31;
    int wm = (warp >> 2) * 64, wn = (warp & 3) * 32;
    int g = lane >> 2, tg = lane & 3;

    #pragma unroll
    for (int it=0; it<8; it++){
        int idx = tid + it*256;
        int r = idx >> 4, c = idx & 15;
        *(uint4*)&As[r*ASTR + c*8] = *(const uint4*)&A[(long long)(bm+r)*128 + c*8];
    }
    if (transB){
        #pragma unroll
        for (int it=0; it<8; it++){
            int idx = tid + it*256;
            int r = idx >> 4, c = idx & 15;
            *(uint4*)&Bs[r*ASTR + c*8] = *(const uint4*)&B[(long long)(bn+r)*128 + c*8];
        }
    } else {
        #pragma unroll
        for (int it=0; it<8; it++){
            int idx = tid + it*256;
            int kr = idx >> 4, nq = idx & 15;
            union { uint4 u; __half h[8]; } vv;
            vv.u = *(const uint4*)&B[(long long)kr*N + bn + nq*8];
            #pragma unroll
            for (int j=0;j<8;j++) Bs[(nq*8+j)*ASTR + kr] = vv.h[j];
        }
    }
    __syncthreads();

    float acc[4][4][4];
    #pragma unroll
    for (int mi=0;mi<4;mi++)
        #pragma unroll
        for (int ni=0;ni<4;ni++)
            #pragma unroll
            for (int q=0;q<4;q++) acc[mi][ni][q] = 0.0f;
    #pragma unroll
    for (int kk=0; kk<128; kk+=16){
        unsigned af[4][4], bf[4][2];
        loadA(af, As, wm, g, tg, kk);
        loadB(bf, Bs, wn, g, tg, kk);
        #pragma unroll
        for (int mi=0;mi<4;mi++)
            #pragma unroll
            for (int ni=0;ni<4;ni++) mma16816(acc[mi][ni], af[mi], bf[ni]);
    }

    #pragma unroll
    for (int mi=0;mi<4;mi++){
        #pragma unroll
        for (int ni=0;ni<4;ni++){
            long long r0 = bm + wm + mi*16 + g;
            int c0 = bn + wn + ni*8 + 2*tg;
            float v0 = acc[mi][ni][0]*alpha, v1 = acc[mi][ni][1]*alpha;
            float v2 = acc[mi][ni][2]*alpha, v3 = acc[mi][ni][3]*alpha;
            if (Cf){
                *(float2*)&Cf[cOff + r0*N + c0]     = make_float2(v0, v1);
                *(float2*)&Cf[cOff + (r0+8)*N + c0] = make_float2(v2, v3);
            }
            if (Ch){
                *(__half2*)&Ch[cOff + r0*N + c0]     = __floats2half2_rn(v0, v1);
                *(__half2*)&Ch[cOff + (r0+8)*N + c0] = __floats2half2_rn(v2, v3);
            }
        }
    }
}

// ---------------- generic chunked fp16 GEMM (used for attn@V, K<=512) ------
#define HSK 40
__global__ void k_hgemm(const __half* __restrict__ A, const __half* __restrict__ B,
                        float* __restrict__ Cf, __half* __restrict__ Ch,
                        int M, int N, int K,
                        long long sA, long long sB, long long sC,
                        float alpha, int transB, int causal)
{
    A += (long long)blockIdx.z * sA;
    B += (long long)blockIdx.z * sB;
    long long cOff = (long long)blockIdx.z * sC;
    int bm = blockIdx.y * 128, bn = blockIdx.x * 128;
    if (causal == 1 && bn >= bm + 128) return;
    int kend = (causal == 2) ? min(K, bm + 128) : K;

    __shared__ __half As[128][HSK];
    __shared__ __half Bs[128][HSK];
    int tid = threadIdx.x;
    int warp = tid >> 5, lane = tid & 31;
    int wm = (warp >> 2) * 64, wn = (warp & 3) * 32;
    int g = lane >> 2, tg = lane & 3;

    float acc[4][4][4];
    #pragma unroll
    for (int mi=0;mi<4;mi++)
        #pragma unroll
        for (int ni=0;ni<4;ni++)
            #pragma unroll
            for (int q=0;q<4;q++) acc[mi][ni][q] = 0.0f;

    for (int k0 = 0; k0 < kend; k0 += 32){
        #pragma unroll
        for (int it=0; it<2; it++){
            int c = tid + it*256;
            int r = c >> 2, q = c & 3;
            *(uint4*)&As[r][q*8] = *(const uint4*)&A[(long long)(bm+r)*K + k0 + q*8];
        }
        if (transB){
            #pragma unroll
            for (int it=0; it<2; it++){
                int c = tid + it*256;
                int r = c >> 2, q = c & 3;
                *(uint4*)&Bs[r][q*8] = *(const uint4*)&B[(long long)(bn+r)*K + k0 + q*8];
            }
        } else {
            #pragma unroll
            for (int it=0; it<2; it++){
                int c = tid + it*256;
                int kr = c >> 4, nq = c & 15;
                union { uint4 u; __half h[8]; } vv;
                vv.u = *(const uint4*)&B[(long long)(k0+kr)*N + bn + nq*8];
                #pragma unroll
                for (int j=0;j<8;j++) Bs[nq*8+j][kr] = vv.h[j];
            }
        }
        __syncthreads();
        #pragma unroll
        for (int kk=0; kk<32; kk+=16){
            unsigned af[4][4], bf[4][2];
            #pragma unroll
            for (int mi=0;mi<4;mi++){
                const __half* pa = &As[wm + mi*16 + g][kk + 2*tg];
                af[mi][0] = *(const unsigned*)pa;
                af[mi][1] = *(const unsigned*)(pa + 8*HSK);
                af[mi][2] = *(const unsigned*)(pa + 8);
                af[mi][3] = *(const unsigned*)(pa + 8*HSK + 8);
            }
            #pragma unroll
            for (int ni=0;ni<4;ni++){
                const __half* pb = &Bs[wn + ni*8 + g][kk + 2*tg];
                bf[ni][0] = *(const unsigned*)pb;
                bf[ni][1] = *(const unsigned*)(pb + 8);
            }
            #pragma unroll
            for (int mi=0;mi<4;mi++)
                #pragma unroll
                for (int ni=0;ni<4;ni++) mma16816(acc[mi][ni], af[mi], bf[ni]);
        }
        __syncthreads();
    }

    #pragma unroll
    for (int mi=0;mi<4;mi++){
        #pragma unroll
        for (int ni=0;ni<4;ni++){
            long long r0 = bm + wm + mi*16 + g;
            int c0 = bn + wn + ni*8 + 2*tg;
            float v0 = acc[mi][ni][0]*alpha, v1 = acc[mi][ni][1]*alpha;
            float v2 = acc[mi][ni][2]*alpha, v3 = acc[mi][ni][3]*alpha;
            if (Cf){
                *(float2*)&Cf[cOff + r0*N + c0]     = make_float2(v0, v1);
                *(float2*)&Cf[cOff + (r0+8)*N + c0] = make_float2(v2, v3);
            }
            if (Ch){
                *(__half2*)&Ch[cOff + r0*N + c0]     = __floats2half2_rn(v0, v1);
                *(__half2*)&Ch[cOff + (r0+8)*N + c0] = __floats2half2_rn(v2, v3);
            }
        }
    }
}

// ---------------- fused out-proj + residual(Q,cape) + LN2 ----------------
__global__ void k_oproj_ln(const __half* __restrict__ hA, const float* __restrict__ W,
                           const float* __restrict__ bias,
                           const float* __restrict__ Qres, const float* __restrict__ cape,
                           const float* __restrict__ ls, const float* __restrict__ lb,
                           float* __restrict__ s2, __half* __restrict__ hs2)
{
    extern __shared__ __half sm[];
    __half* As = sm;
    __half* Ws = sm + 128*ASTR;
    float*  Vs = (float*)sm;          // reused after MMA: [128][132]
    int tid = threadIdx.x;
    int warp = tid >> 5, lane = tid & 31;
    int wm = (warp >> 2) * 64, wn = (warp & 3) * 32;
    int g = lane >> 2, tg = lane & 3;
    long long bm = (long long)blockIdx.x * 128;

    #pragma unroll
    for (int it=0; it<8; it++){
        int idx = tid + it*256;
        int r = idx >> 4, c = idx & 15;
        *(uint4*)&As[r*ASTR + c*8] = *(const uint4*)&hA[(bm+r)*128 + c*8];
    }
    #pragma unroll
    for (int it=0; it<16; it++){
        int idx = tid + it*256;
        int r = idx >> 5, c4 = idx & 31;
        float4 vw = *(const float4*)&W[(long long)r*128 + c4*4];
        __half2* pw = (__half2*)&Ws[r*ASTR + c4*4];
        pw[0] = __floats2half2_rn(vw.x, vw.y);
        pw[1] = __floats2half2_rn(vw.z, vw.w);
    }
    __syncthreads();

    float acc[4][4][4];
    #pragma unroll
    for (int mi=0;mi<4;mi++)
        #pragma unroll
        for (int ni=0;ni<4;ni++)
            #pragma unroll
            for (int q=0;q<4;q++) acc[mi][ni][q] = 0.0f;
    #pragma unroll
    for (int kk=0; kk<128; kk+=16){
        unsigned af[4][4], bf[4][2];
        loadA(af, As, wm, g, tg, kk);
        loadB(bf, Ws, wn, g, tg, kk);
        #pragma unroll
        for (int mi=0;mi<4;mi++)
            #pragma unroll
            for (int ni=0;ni<4;ni++) mma16816(acc[mi][ni], af[mi], bf[ni]);
    }
    __syncthreads();   // done reading As/Ws; safe to alias Vs

    #pragma unroll
    for (int mi=0;mi<4;mi++){
        int rl = wm + mi*16 + g;
        long long gr = bm + rl;
        float cp0 = cape[gr], cp1 = cape[gr+8];
        #pragma unroll
        for (int ni=0;ni<4;ni++){
            int c0 = wn + ni*8 + 2*tg;
            float b0 = bias[c0], b1 = bias[c0+1];
            float2 q0 = *(const float2*)&Qres[gr*128 + c0];
            float2 q1 = *(const float2*)&Qres[(gr+8)*128 + c0];
            Vs[rl*132 + c0]       = acc[mi][ni][0] + b0 + q0.x + cp0;
            Vs[rl*132 + c0 + 1]   = acc[mi][ni][1] + b1 + q0.y + cp0;
            Vs[(rl+8)*132 + c0]   = acc[mi][ni][2] + b0 + q1.x + cp1;
            Vs[(rl+8)*132 + c0+1] = acc[mi][ni][3] + b1 + q1.y + cp1;
        }
    }
    __syncthreads();

    // per-row LN: warp handles 16 rows
    float4 sv = *(const float4*)&ls[lane*4];
    float4 bv = *(const float4*)&lb[lane*4];
    for (int rr=0; rr<16; rr++){
        int r = warp*16 + rr;
        long long gr = bm + r;
        float4 x = *(const float4*)&Vs[r*132 + lane*4];
        float mean = warpSum(x.x+x.y+x.z+x.w) * (1.0f/D);
        float cx=x.x-mean, cy=x.y-mean, cz=x.z-mean, cw=x.w-mean;
        float var = warpSum(cx*cx+cy*cy+cz*cz+cw*cw) * (1.0f/D);
        float rstd = rsqrtf(var + 1e-8f);
        float o0 = cx*rstd*sv.x+bv.x, o1 = cy*rstd*sv.y+bv.y;
        float o2 = cz*rstd*sv.z+bv.z, o3 = cw*rstd*sv.w+bv.w;
        *(float4*)&s2[gr*128 + lane*4] = make_float4(o0,o1,o2,o3);
        __half2* hp = (__half2*)&hs2[gr*128 + lane*4];
        hp[0] = __floats2half2_rn(o0,o1);
        hp[1] = __floats2half2_rn(o2,o3);
    }
}

// ---------------- fused FFN: out = resid + relu(A@W1^T+b1)@W2^T + b2 -------
__global__ void k_ffn(const __half* __restrict__ hA, const float* __restrict__ resid,
                      const float* __restrict__ W1, const float* __restrict__ b1,
                      const float* __restrict__ W2, const float* __restrict__ b2,
                      float* __restrict__ outF, __half* __restrict__ outH)
{
    extern __shared__ __half sm[];
    __half* As = sm;
    __half* Ws = sm + 128*ASTR;
    __half* Hs = As;     // alias after MMA1
    int tid = threadIdx.x;
    int warp = tid >> 5, lane = tid & 31;
    int wm = (warp >> 2) * 64, wn = (warp & 3) * 32;
    int g = lane >> 2, tg = lane & 3;
    long long bm = (long long)blockIdx.x * 128;

    #pragma unroll
    for (int it=0; it<8; it++){
        int idx = tid + it*256;
        int r = idx >> 4, c = idx & 15;
        *(uint4*)&As[r*ASTR + c*8] = *(const uint4*)&hA[(bm+r)*128 + c*8];
    }
    #pragma unroll
    for (int it=0; it<16; it++){
        int idx = tid + it*256;
        int r = idx >> 5, c4 = idx & 31;
        float4 vw = *(const float4*)&W1[(long long)r*128 + c4*4];
        __half2* pw = (__half2*)&Ws[r*ASTR + c4*4];
        pw[0] = __floats2half2_rn(vw.x, vw.y);
        pw[1] = __floats2half2_rn(vw.z, vw.w);
    }
    __syncthreads();

    float acc[4][4][4];
    #pragma unroll
    for (int mi=0;mi<4;mi++)
        #pragma unroll
        for (int ni=0;ni<4;ni++)
            #pragma unroll
            for (int q=0;q<4;q++) acc[mi][ni][q] = 0.0f;
    #pragma unroll
    for (int kk=0; kk<128; kk+=16){
        unsigned af[4][4], bf[4][2];
        loadA(af, As, wm, g, tg, kk);
        loadB(bf, Ws, wn, g, tg, kk);
        #pragma unroll
        for (int mi=0;mi<4;mi++)
            #pragma unroll
            for (int ni=0;ni<4;ni++) mma16816(acc[mi][ni], af[mi], bf[ni]);
    }
    __syncthreads();   // MMA1 done: As & Ws dead

    // h = relu(acc + b1) -> Hs (aliases As); load W2 -> Ws
    #pragma unroll
    for (int mi=0;mi<4;mi++){
        int rl = wm + mi*16 + g;
        #pragma unroll
        for (int ni=0;ni<4;ni++){
            int c0 = wn + ni*8 + 2*tg;
            float b0 = b1[c0], bb1 = b1[c0+1];
            float h0 = fmaxf(acc[mi][ni][0]+b0, 0.0f);
            float h1 = fmaxf(acc[mi][ni][1]+bb1, 0.0f);
            float h2 = fmaxf(acc[mi][ni][2]+b0, 0.0f);
            float h3 = fmaxf(acc[mi][ni][3]+bb1, 0.0f);
            *(__half2*)&Hs[rl*ASTR + c0]     = __floats2half2_rn(h0, h1);
            *(__half2*)&Hs[(rl+8)*ASTR + c0] = __floats2half2_rn(h2, h3);
        }
    }
    #pragma unroll
    for (int it=0; it<16; it++){
        int idx = tid + it*256;
        int r = idx >> 5, c4 = idx & 31;
        float4 vw = *(const float4*)&W2[(long long)r*128 + c4*4];
        __half2* pw = (__half2*)&Ws[r*ASTR + c4*4];
        pw[0] = __floats2half2_rn(vw.x, vw.y);
        pw[1] = __floats2half2_rn(vw.z, vw.w);
    }
    __syncthreads();

    #pragma unroll
    for (int mi=0;mi<4;mi++)
        #pragma unroll
        for (int ni=0;ni<4;ni++)
            #pragma unroll
            for (int q=0;q<4;q++) acc[mi][ni][q] = 0.0f;
    #pragma unroll
    for (int kk=0; kk<128; kk+=16){
        unsigned af[4][4], bf[4][2];
        loadA(af, Hs, wm, g, tg, kk);
        loadB(bf, Ws, wn, g, tg, kk);
        #pragma unroll
        for (int mi=0;mi<4;mi++)
            #pragma unroll
            for (int ni=0;ni<4;ni++) mma16816(acc[mi][ni], af[mi], bf[ni]);
    }

    #pragma unroll
    for (int mi=0;mi<4;mi++){
        int rl = wm + mi*16 + g;
        long long gr = bm + rl;
        #pragma unroll
        for (int ni=0;ni<4;ni++){
            int c0 = wn + ni*8 + 2*tg;
            float b0 = b2[c0], bb1 = b2[c0+1];
            float2 r0v = *(const float2*)&resid[gr*128 + c0];
            float2 r1v = *(const float2*)&resid[(gr+8)*128 + c0];
            float v0 = acc[mi][ni][0]+b0+r0v.x, v1 = acc[mi][ni][1]+bb1+r0v.y;
            float v2 = acc[mi][ni][2]+b0+r1v.x, v3 = acc[mi][ni][3]+bb1+r1v.y;
            *(float2*)&outF[gr*128 + c0]     = make_float2(v0, v1);
            *(float2*)&outF[(gr+8)*128 + c0] = make_float2(v2, v3);
            *(__half2*)&outH[gr*128 + c0]     = __floats2half2_rn(v0, v1);
            *(__half2*)&outH[(gr+8)*128 + c0] = __floats2half2_rn(v2, v3);
        }
    }
}

// ---------------- softmax + CAPE, warp per row, chunk-strided ----------------
__global__ void k_softmax_cape2(const __half* __restrict__ scores, const __half* __restrict__ hE,
                                __half* __restrict__ hattn, float* __restrict__ cape)
{
    int warp = threadIdx.x >> 5, lane = threadIdx.x & 31;
    long long row = (long long)blockIdx.x * 8 + warp;
    int qi = (int)(row & (L-1));
    __shared__ __half smE[8][L];
    {
        uint4* dst = (uint4*)&smE[warp][0];
        const uint4* src = (const uint4*)(hE + row*L);
        dst[lane] = src[lane];
        dst[lane+32] = src[lane+32];
    }
    __syncwarp();

    const __half* Sr = scores + row*L;
    __half* Ar = hattn + row*L;
    int nch = qi >> 5;               // last chunk with any valid element

    float sv[16];
    float m = -3.0e38f;
    #pragma unroll
    for (int j=0;j<16;j++){
        if (j <= nch){
            int k = j*32 + lane;
            float x = __half2float(Sr[k]);
            sv[j] = (k <= qi) ? x : -3.0e38f;
            m = fmaxf(m, sv[j]);
        } else sv[j] = -3.0e38f;
    }
    m = warpMax(m);

    float zs = 0.0f;
    #pragma unroll
    for (int j=0;j<16;j++){
        if (j <= nch){
            float t = (sv[j] > -1.0e37f) ? __expf(sv[j]-m) : 0.0f;
            sv[j] = t; zs += t;
        } else sv[j] = 0.0f;
    }
    float Z = warpSum(zs);
    float invZ = 1.0f / Z;

    float intra[16], ctot[16];
    #pragma unroll
    for (int j=0;j<16;j++){
        int k = j*32 + lane;
        if (j <= nch){
            float a = sv[j]*invZ;
            Ar[k] = __float2half(a);
            float G;
            if (k <= qi){
                float t = __expf(-a);
                G = __fdividef(t, 1.0f + t);   // 1 - sigmoid(a)
            } else G = 0.5f;
            float v = G;
            #pragma unroll
            for (int off=1; off<32; off<<=1){
                float tt = __shfl_down_sync(0xffffffffu, v, off);
                if (lane + off < 32) v += tt;
            }
            intra[j] = v;
            ctot[j] = __shfl_sync(0xffffffffu, v, 0);
        } else {
            Ar[k] = __float2half(0.0f);
            intra[j] = 0.5f * (32 - lane);
            ctot[j] = 16.0f;
        }
    }

    float running = 0.0f, cv = 0.0f;
    #pragma unroll
    for (int j=15;j>=0;j--){
        float P = intra[j] + running;
        running += ctot[j];
        P = fminf(P, (float)(L-1));
        float Pf = floorf(P);
        float frac = P - Pf;
        int i0 = (int)Pf;
        int i1 = (int)ceilf(P);
        cv += frac*__half2float(smE[warp][i1]) + (1.0f-frac)*__half2float(smE[warp][i0]);
    }
    cv = warpSum(cv);
    if (lane==0) cape[row] = cv * (1.0f/L);
}

// ---------------- host orchestration ----------------
extern "C" void kernel_launch(void* const* d_in, const int* in_sizes, int n_in,
                              void* d_out, int out_size)
{
    const float* item_emb = (const float*)d_in[0];
    const float* pos_emb  = (const float*)d_in[1];
    const float* pre_w    = (const float*)d_in[2];
    const float* pre_b    = (const float*)d_in[3];
    const float* ln1_s    = (const float*)d_in[4];
    const float* ln1_b    = (const float*)d_in[5];
    const float* in_w     = (const float*)d_in[6];
    const float* in_b     = (const float*)d_in[7];
    const float* out_w    = (const float*)d_in[8];
    const float* out_b    = (const float*)d_in[9];
    const float* ln2_s    = (const float*)d_in[10];
    const float* ln2_b    = (const float*)d_in[11];
    const float* c1_w     = (const float*)d_in[12];
    const float* c1_b     = (const float*)d_in[13];
    const float* c2_w     = (const float*)d_in[14];
    const float* c2_b     = (const float*)d_in[15];
    const float* lnf_s    = (const float*)d_in[16];
    const float* lnf_b    = (const float*)d_in[17];
    const int* log_seqs   = (const int*)d_in[19];
    const int* pos_seqs   = (const int*)d_in[20];
    const int* neg_seqs   = (const int*)d_in[21];
    float* out = (float*)d_out;

    float *seqs,*Q,*s2,*cape;
    __half *hseqs,*hQ,*hs2,*hq,*hk,*hv,*hqp,*hmha,*hscores,*hattn,*hE,*hpos;
    cudaGetSymbolAddress((void**)&seqs,   g_seqs);
    cudaGetSymbolAddress((void**)&Q,      g_Q);
    cudaGetSymbolAddress((void**)&s2,     g_s2);
    cudaGetSymbolAddress((void**)&cape,   g_cape);
    cudaGetSymbolAddress((void**)&hseqs,  g_hseqs);
    cudaGetSymbolAddress((void**)&hQ,     g_hQ);
    cudaGetSymbolAddress((void**)&hs2,    g_hs2);
    cudaGetSymbolAddress((void**)&hq,     g_hq);
    cudaGetSymbolAddress((void**)&hk,     g_hk);
    cudaGetSymbolAddress((void**)&hv,     g_hv);
    cudaGetSymbolAddress((void**)&hqp,    g_hqp);
    cudaGetSymbolAddress((void**)&hmha,   g_hmha);
    cudaGetSymbolAddress((void**)&hscores,g_hscores);
    cudaGetSymbolAddress((void**)&hattn,  g_hattn);
    cudaGetSymbolAddress((void**)&hE,     g_hE);
    cudaGetSymbolAddress((void**)&hpos,   g_hpos);

    cudaFuncSetAttribute(k_qkvp,     cudaFuncAttributeMaxDynamicSharedMemorySize, 3*TILE_B);
    cudaFuncSetAttribute(k_hgemm128, cudaFuncAttributeMaxDynamicSharedMemorySize, 2*TILE_B);
    cudaFuncSetAttribute(k_oproj_ln, cudaFuncAttributeMaxDynamicSharedMemorySize, 2*TILE_B);
    cudaFuncSetAttribute(k_ffn,      cudaFuncAttributeMaxDynamicSharedMemorySize, 2*TILE_B);

    const float inv_sqrt_d = 1.0f / sqrtf((float)D);

    k_embed<<<BL/8, 256>>>(item_emb, log_seqs, seqs, hseqs, sqrtf((float)D));
    k_f2h<<<(D*L+255)/256, 256>>>(pos_emb, hpos, D*L);

    for (int i = 0; i < NBLK; i++){
        const float* wq = in_w + (long long)i*3*D*D;
        const float* wk = wq + (long long)D*D;
        const float* wv = wk + (long long)D*D;
        const float* bq = in_b + (long long)i*3*D;

        k_ln_dual<<<BL/8, 256>>>(seqs, Q, hQ, ln1_s + i*D, ln1_b + i*D);
        k_qkvp<<<BL/128, 256, 3*TILE_B>>>(hQ, hseqs, wq, wk, wv, pre_w, bq, pre_b,
                                          hq, hk, hv, hqp);
        k_hgemm128<<<dim3(L/128, L/128, Bb), 256, 2*TILE_B>>>(
            hq, hk, 0, hscores, L,
            (long long)L*D, (long long)L*D, (long long)L*L, inv_sqrt_d, 1, 1);
        k_hgemm128<<<dim3(L/128, BL/128, 1), 256, 2*TILE_B>>>(
            hqp, hpos, 0, hE, L, 0, 0, 0, 1.0f, 0, 0);
        k_softmax_cape2<<<BL/8, 256>>>(hscores, hE, hattn, cape);
        k_hgemm<<<dim3(D/128, L/128, Bb), 256>>>(
            hattn, hv, 0, hmha, L, D, L,
            (long long)L*L, (long long)L*D, (long long)L*D, 1.0f, 0, 2);
        k_oproj_ln<<<BL/128, 256, 2*TILE_B>>>(
            hmha, out_w + (long long)i*D*D, out_b + i*D, Q, cape,
            ln2_s + i*D, ln2_b + i*D, s2, hs2);
        k_ffn<<<BL/128, 256, 2*TILE_B>>>(
            hs2, s2, c1_w + (long long)i*D*D, c1_b + i*D,
            c2_w + (long long)i*D*D, c2_b + i*D, seqs, hseqs);
    }

    k_lnlogits<<<BL, D>>>(seqs, lnf_s, lnf_b, item_emb, pos_seqs, neg_seqs, out);
}

// round 5
// speedup vs baseline: 5.4297x; 1.1917x over previous
#include <cuda_runtime.h>
#include <cuda_fp16.h>
#include <math.h>

#define D 128
#define L 512
#define Bb 128
#define BL (Bb*L)   // 65536 tokens
#define NBLK 2
#define ASTR 136                      // smem row stride in halfs
#define TILE_B (128*ASTR*2)           // 34816 bytes per fp16 tile

// ---------------- scratch (device globals; no allocations allowed) ----------
__device__ float  g_seqs [(size_t)BL*D];
__device__ float  g_Q    [(size_t)BL*D];
__device__ float  g_s2   [(size_t)BL*D];
__device__ float  g_cape [BL];
__device__ __half g_hseqs[(size_t)BL*D];
__device__ __half g_hQ   [(size_t)BL*D];
__device__ __half g_hs2  [(size_t)BL*D];
__device__ __half g_hq   [(size_t)BL*D];
__device__ __half g_hk   [(size_t)BL*D];
__device__ __half g_hv   [(size_t)BL*D];
__device__ __half g_hqp  [(size_t)BL*D];
__device__ __half g_hmha [(size_t)BL*D];
__device__ __half g_hscores[(size_t)BL*L];
__device__ __half g_hattn[(size_t)BL*L];
__device__ __half g_hE   [(size_t)BL*L];
__device__ __half g_hpos [(size_t)D*L];
// fp16 weights: [0]=in_w (6*D*D), [98304]=pre_w, [114688]=out_w(2), [147456]=c1(2), [180224]=c2(2)
__device__ __half g_hw   [13*(size_t)D*D];

// ---------------- helpers ----------------
__device__ __forceinline__ float warpSum(float v){
    #pragma unroll
    for (int o=16;o;o>>=1) v += __shfl_xor_sync(0xffffffffu, v, o);
    return v;
}
__device__ __forceinline__ float warpMax(float v){
    #pragma unroll
    for (int o=16;o;o>>=1) v = fmaxf(v, __shfl_xor_sync(0xffffffffu, v, o));
    return v;
}
__device__ __forceinline__ void mma16816(float* c, const unsigned* a, const unsigned* b){
    asm volatile(
        "mma.sync.aligned.m16n8k16.row.col.f32.f16.f16.f32 "
        "{%0,%1,%2,%3}, {%4,%5,%6,%7}, {%8,%9}, {%0,%1,%2,%3};\n"
        : "+f"(c[0]),"+f"(c[1]),"+f"(c[2]),"+f"(c[3])
        : "r"(a[0]),"r"(a[1]),"r"(a[2]),"r"(a[3]), "r"(b[0]),"r"(b[1]));
}
__device__ __forceinline__ void loadA(unsigned af[4][4], const __half* As, int wm, int g, int tg, int kk){
    #pragma unroll
    for (int mi=0;mi<4;mi++){
        const __half* pa = &As[(wm + mi*16 + g)*ASTR + kk + 2*tg];
        af[mi][0] = *(const unsigned*)pa;
        af[mi][1] = *(const unsigned*)(pa + 8*ASTR);
        af[mi][2] = *(const unsigned*)(pa + 8);
        af[mi][3] = *(const unsigned*)(pa + 8*ASTR + 8);
    }
}
__device__ __forceinline__ void loadB(unsigned bf[4][2], const __half* Bs, int wn, int g, int tg, int kk){
    #pragma unroll
    for (int ni=0;ni<4;ni++){
        const __half* pb = &Bs[(wn + ni*8 + g)*ASTR + kk + 2*tg];
        bf[ni][0] = *(const unsigned*)pb;
        bf[ni][1] = *(const unsigned*)(pb + 8);
    }
}
// copy a 128x128 fp16 weight into smem tile (stride ASTR), 256 threads
__device__ __forceinline__ void loadW16(__half* Ws, const __half* W, int tid){
    #pragma unroll
    for (int it=0; it<8; it++){
        int idx = tid + it*256;
        int r = idx >> 4, c = idx & 15;
        *(uint4*)&Ws[r*ASTR + c*8] = *(const uint4*)&W[(long long)r*128 + c*8];
    }
}

// ---------------- embedding gather (warp per token) ----------------
__global__ void k_embed(const float* __restrict__ emb, const int* __restrict__ ids,
                        float* __restrict__ out, __half* __restrict__ hout, float scale){
    int warp = threadIdx.x >> 5, lane = threadIdx.x & 31;
    long long row = (long long)blockIdx.x * 8 + warp;
    long long idx = ids[row];
    float4 v = *(const float4*)&emb[idx*D + lane*4];
    v.x*=scale; v.y*=scale; v.z*=scale; v.w*=scale;
    *(float4*)&out[row*D + lane*4] = v;
    __half2* hp = (__half2*)&hout[row*D + lane*4];
    hp[0] = __floats2half2_rn(v.x, v.y);
    hp[1] = __floats2half2_rn(v.z, v.w);
}

__global__ void k_f2h(const float* __restrict__ x, __half* __restrict__ y, int n){
    int i = blockIdx.x*256 + threadIdx.x;
    if (i < n) y[i] = __float2half(x[i]);
}

// ---------------- layernorm, warp per token, dual output ----------------
__global__ void k_ln_dual(const float* __restrict__ x, float* __restrict__ y,
                          __half* __restrict__ hy,
                          const float* __restrict__ s, const float* __restrict__ b){
    int warp = threadIdx.x >> 5, lane = threadIdx.x & 31;
    long long row = (long long)blockIdx.x * 8 + warp;
    float4 v = *(const float4*)&x[row*D + lane*4];
    float mean = warpSum(v.x+v.y+v.z+v.w) * (1.0f/D);
    float cx=v.x-mean, cy=v.y-mean, cz=v.z-mean, cw=v.w-mean;
    float var = warpSum(cx*cx+cy*cy+cz*cz+cw*cw) * (1.0f/D);
    float rstd = rsqrtf(var + 1e-8f);
    float4 sv = *(const float4*)&s[lane*4];
    float4 bv = *(const float4*)&b[lane*4];
    float o0 = cx*rstd*sv.x+bv.x, o1 = cy*rstd*sv.y+bv.y;
    float o2 = cz*rstd*sv.z+bv.z, o3 = cw*rstd*sv.w+bv.w;
    *(float4*)&y[row*D + lane*4] = make_float4(o0,o1,o2,o3);
    __half2* hp = (__half2*)&hy[row*D + lane*4];
    hp[0] = __floats2half2_rn(o0,o1);
    hp[1] = __floats2half2_rn(o2,o3);
}

// ---------------- fused final LN + logits (warp per token) ----------------
__global__ void k_lnlogits(const float* __restrict__ x, const float* __restrict__ s,
                           const float* __restrict__ b, const float* __restrict__ emb,
                           const int* __restrict__ pos, const int* __restrict__ neg,
                           float* __restrict__ out){
    int warp = threadIdx.x >> 5, lane = threadIdx.x & 31;
    long long row = (long long)blockIdx.x * 8 + warp;
    float4 v = *(const float4*)&x[row*D + lane*4];
    float mean = warpSum(v.x+v.y+v.z+v.w) * (1.0f/D);
    float cx=v.x-mean, cy=v.y-mean, cz=v.z-mean, cw=v.w-mean;
    float var = warpSum(cx*cx+cy*cy+cz*cz+cw*cw) * (1.0f/D);
    float rstd = rsqrtf(var + 1e-8f);
    float4 sv = *(const float4*)&s[lane*4];
    float4 bv = *(const float4*)&b[lane*4];
    float f0 = cx*rstd*sv.x+bv.x, f1 = cy*rstd*sv.y+bv.y;
    float f2 = cz*rstd*sv.z+bv.z, f3 = cw*rstd*sv.w+bv.w;
    long long pi = pos[row], ni = neg[row];
    float4 pe = *(const float4*)&emb[pi*D + lane*4];
    float4 ne = *(const float4*)&emb[ni*D + lane*4];
    float sp = warpSum(f0*pe.x + f1*pe.y + f2*pe.z + f3*pe.w);
    float sn = warpSum(f0*ne.x + f1*ne.y + f2*ne.z + f3*ne.w);
    if (lane==0){
        out[row]                 = sp;
        out[(long long)BL + row] = sn;
    }
}

// ---------------- QKV + pre_proj: grid (BL/128, 4), one weight per block ----
__global__ void __launch_bounds__(256, 2)
k_qkvp2(const __half* __restrict__ hQ, const __half* __restrict__ hS,
        const __half* __restrict__ hw_in, const __half* __restrict__ hw_pre,
        const float* __restrict__ b012, const float* __restrict__ b3,
        __half* __restrict__ o0, __half* __restrict__ o1,
        __half* __restrict__ o2, __half* __restrict__ o3)
{
    extern __shared__ __half sm[];
    __half* As = sm;
    __half* Ws = sm + 128*ASTR;
    int tid = threadIdx.x;
    int warp = tid >> 5, lane = tid & 31;
    int wm = (warp >> 2) * 64, wn = (warp & 3) * 32;
    int g = lane >> 2, tg = lane & 3;
    long long bm = (long long)blockIdx.x * 128;
    int w = blockIdx.y;

    const __half* Asrc = (w==0 || w==3) ? hQ : hS;
    const __half* W = (w<3) ? (hw_in + (long long)w*D*D) : hw_pre;
    #pragma unroll
    for (int it=0; it<8; it++){
        int idx = tid + it*256;
        int r = idx >> 4, c = idx & 15;
        *(uint4*)&As[r*ASTR + c*8] = *(const uint4*)&Asrc[(bm+r)*128 + c*8];
    }
    loadW16(Ws, W, tid);
    __syncthreads();

    float acc[4][4][4];
    #pragma unroll
    for (int mi=0;mi<4;mi++)
        #pragma unroll
        for (int ni=0;ni<4;ni++)
            #pragma unroll
            for (int q=0;q<4;q++) acc[mi][ni][q] = 0.0f;
    #pragma unroll
    for (int kk=0; kk<128; kk+=16){
        unsigned af[4][4], bf[4][2];
        loadA(af, As, wm, g, tg, kk);
        loadB(bf, Ws, wn, g, tg, kk);
        #pragma unroll
        for (int mi=0;mi<4;mi++)
            #pragma unroll
            for (int ni=0;ni<4;ni++) mma16816(acc[mi][ni], af[mi], bf[ni]);
    }

    const float* bias = (w < 3) ? (b012 + w*128) : b3;
    __half* out = (w==0) ? o0 : (w==1) ? o1 : (w==2) ? o2 : o3;
    #pragma unroll
    for (int mi=0;mi<4;mi++){
        #pragma unroll
        for (int ni=0;ni<4;ni++){
            long long r0 = bm + wm + mi*16 + g;
            int c0 = wn + ni*8 + 2*tg;
            float b0 = bias[c0], b1 = bias[c0+1];
            float v0 = acc[mi][ni][0]+b0, v1 = acc[mi][ni][1]+b1;
            float v2 = acc[mi][ni][2]+b0, v3 = acc[mi][ni][3]+b1;
            if (w == 3){
                v0 = __fdividef(v0, 1.0f + __expf(-v0));
                v1 = __fdividef(v1, 1.0f + __expf(-v1));
                v2 = __fdividef(v2, 1.0f + __expf(-v2));
                v3 = __fdividef(v3, 1.0f + __expf(-v3));
            }
            *(__half2*)&out[r0*128 + c0]     = __floats2half2_rn(v0, v1);
            *(__half2*)&out[(r0+8)*128 + c0] = __floats2half2_rn(v2, v3);
        }
    }
}

// ---------------- full-K(=128)-resident fp16 GEMM ----------------
__global__ void __launch_bounds__(256, 2)
k_hgemm128(const __half* __restrict__ A, const __half* __restrict__ B,
           float* __restrict__ Cf, __half* __restrict__ Ch, int N,
           long long sA, long long sB, long long sC,
           float alpha, int transB, int causal)
{
    A += (long long)blockIdx.z * sA;
    B += (long long)blockIdx.z * sB;
    long long cOff = (long long)blockIdx.z * sC;
    int bm = blockIdx.y * 128, bn = blockIdx.x * 128;
    if (causal && bn >= bm + 128) return;

    extern __shared__ __half sm[];
    __half* As = sm;
    __half* Bs = sm + 128*ASTR;
    int tid = threadIdx.x;
    int warp = tid >> 5, lane = tid & 31;
    int wm = (warp >> 2) * 64, wn = (warp & 3) * 32;
    int g = lane >> 2, tg = lane & 3;

    #pragma unroll
    for (int it=0; it<8; it++){
        int idx = tid + it*256;
        int r = idx >> 4, c = idx & 15;
        *(uint4*)&As[r*ASTR + c*8] = *(const uint4*)&A[(long long)(bm+r)*128 + c*8];
    }
    if (transB){
        #pragma unroll
        for (int it=0; it<8; it++){
            int idx = tid + it*256;
            int r = idx >> 4, c = idx & 15;
            *(uint4*)&Bs[r*ASTR + c*8] = *(const uint4*)&B[(long long)(bn+r)*128 + c*8];
        }
    } else {
        #pragma unroll
        for (int it=0; it<8; it++){
            int idx = tid + it*256;
            int kr = idx >> 4, nq = idx & 15;
            union { uint4 u; __half h[8]; } vv;
            vv.u = *(const uint4*)&B[(long long)kr*N + bn + nq*8];
            #pragma unroll
            for (int j=0;j<8;j++) Bs[(nq*8+j)*ASTR + kr] = vv.h[j];
        }
    }
    __syncthreads();

    float acc[4][4][4];
    #pragma unroll
    for (int mi=0;mi<4;mi++)
        #pragma unroll
        for (int ni=0;ni<4;ni++)
            #pragma unroll
            for (int q=0;q<4;q++) acc[mi][ni][q] = 0.0f;
    #pragma unroll
    for (int kk=0; kk<128; kk+=16){
        unsigned af[4][4], bf[4][2];
        loadA(af, As, wm, g, tg, kk);
        loadB(bf, Bs, wn, g, tg, kk);
        #pragma unroll
        for (int mi=0;mi<4;mi++)
            #pragma unroll
            for (int ni=0;ni<4;ni++) mma16816(acc[mi][ni], af[mi], bf[ni]);
    }

    #pragma unroll
    for (int mi=0;mi<4;mi++){
        #pragma unroll
        for (int ni=0;ni<4;ni++){
            long long r0 = bm + wm + mi*16 + g;
            int c0 = bn + wn + ni*8 + 2*tg;
            float v0 = acc[mi][ni][0]*alpha, v1 = acc[mi][ni][1]*alpha;
            float v2 = acc[mi][ni][2]*alpha, v3 = acc[mi][ni][3]*alpha;
            if (Cf){
                *(float2*)&Cf[cOff + r0*N + c0]     = make_float2(v0, v1);
                *(float2*)&Cf[cOff + (r0+8)*N + c0] = make_float2(v2, v3);
            }
            if (Ch){
                *(__half2*)&Ch[cOff + r0*N + c0]     = __floats2half2_rn(v0, v1);
                *(__half2*)&Ch[cOff + (r0+8)*N + c0] = __floats2half2_rn(v2, v3);
            }
        }
    }
}

// ---------------- generic chunked fp16 GEMM (attn@V) ----------------
#define HSK 40
__global__ void __launch_bounds__(256, 2)
k_hgemm(const __half* __restrict__ A, const __half* __restrict__ B,
        float* __restrict__ Cf, __half* __restrict__ Ch,
        int M, int N, int K,
        long long sA, long long sB, long long sC,
        float alpha, int transB, int causal)
{
    A += (long long)blockIdx.z * sA;
    B += (long long)blockIdx.z * sB;
    long long cOff = (long long)blockIdx.z * sC;
    int bm = blockIdx.y * 128, bn = blockIdx.x * 128;
    if (causal == 1 && bn >= bm + 128) return;
    int kend = (causal == 2) ? min(K, bm + 128) : K;

    __shared__ __half As[128][HSK];
    __shared__ __half Bs[128][HSK];
    int tid = threadIdx.x;
    int warp = tid >> 5, lane = tid & 31;
    int wm = (warp >> 2) * 64, wn = (warp & 3) * 32;
    int g = lane >> 2, tg = lane & 3;

    float acc[4][4][4];
    #pragma unroll
    for (int mi=0;mi<4;mi++)
        #pragma unroll
        for (int ni=0;ni<4;ni++)
            #pragma unroll
            for (int q=0;q<4;q++) acc[mi][ni][q] = 0.0f;

    for (int k0 = 0; k0 < kend; k0 += 32){
        #pragma unroll
        for (int it=0; it<2; it++){
            int c = tid + it*256;
            int r = c >> 2, q = c & 3;
            *(uint4*)&As[r][q*8] = *(const uint4*)&A[(long long)(bm+r)*K + k0 + q*8];
        }
        if (transB){
            #pragma unroll
            for (int it=0; it<2; it++){
                int c = tid + it*256;
                int r = c >> 2, q = c & 3;
                *(uint4*)&Bs[r][q*8] = *(const uint4*)&B[(long long)(bn+r)*K + k0 + q*8];
            }
        } else {
            #pragma unroll
            for (int it=0; it<2; it++){
                int c = tid + it*256;
                int kr = c >> 4, nq = c & 15;
                union { uint4 u; __half h[8]; } vv;
                vv.u = *(const uint4*)&B[(long long)(k0+kr)*N + bn + nq*8];
                #pragma unroll
                for (int j=0;j<8;j++) Bs[nq*8+j][kr] = vv.h[j];
            }
        }
        __syncthreads();
        #pragma unroll
        for (int kk=0; kk<32; kk+=16){
            unsigned af[4][4], bf[4][2];
            #pragma unroll
            for (int mi=0;mi<4;mi++){
                const __half* pa = &As[wm + mi*16 + g][kk + 2*tg];
                af[mi][0] = *(const unsigned*)pa;
                af[mi][1] = *(const unsigned*)(pa + 8*HSK);
                af[mi][2] = *(const unsigned*)(pa + 8);
                af[mi][3] = *(const unsigned*)(pa + 8*HSK + 8);
            }
            #pragma unroll
            for (int ni=0;ni<4;ni++){
                const __half* pb = &Bs[wn + ni*8 + g][kk + 2*tg];
                bf[ni][0] = *(const unsigned*)pb;
                bf[ni][1] = *(const unsigned*)(pb + 8);
            }
            #pragma unroll
            for (int mi=0;mi<4;mi++)
                #pragma unroll
                for (int ni=0;ni<4;ni++) mma16816(acc[mi][ni], af[mi], bf[ni]);
        }
        __syncthreads();
    }

    #pragma unroll
    for (int mi=0;mi<4;mi++){
        #pragma unroll
        for (int ni=0;ni<4;ni++){
            long long r0 = bm + wm + mi*16 + g;
            int c0 = bn + wn + ni*8 + 2*tg;
            float v0 = acc[mi][ni][0]*alpha, v1 = acc[mi][ni][1]*alpha;
            float v2 = acc[mi][ni][2]*alpha, v3 = acc[mi][ni][3]*alpha;
            if (Cf){
                *(float2*)&Cf[cOff + r0*N + c0]     = make_float2(v0, v1);
                *(float2*)&Cf[cOff + (r0+8)*N + c0] = make_float2(v2, v3);
            }
            if (Ch){
                *(__half2*)&Ch[cOff + r0*N + c0]     = __floats2half2_rn(v0, v1);
                *(__half2*)&Ch[cOff + (r0+8)*N + c0] = __floats2half2_rn(v2, v3);
            }
        }
    }
}

// ---------------- fused out-proj + residual(Q,cape) + LN2 ----------------
__global__ void __launch_bounds__(256, 2)
k_oproj_ln(const __half* __restrict__ hA, const __half* __restrict__ W,
           const float* __restrict__ bias,
           const float* __restrict__ Qres, const float* __restrict__ cape,
           const float* __restrict__ ls, const float* __restrict__ lb,
           float* __restrict__ s2, __half* __restrict__ hs2)
{
    extern __shared__ __half sm[];
    __half* As = sm;
    __half* Ws = sm + 128*ASTR;
    float*  Vs = (float*)sm;          // reused after MMA: [128][132]
    int tid = threadIdx.x;
    int warp = tid >> 5, lane = tid & 31;
    int wm = (warp >> 2) * 64, wn = (warp & 3) * 32;
    int g = lane >> 2, tg = lane & 3;
    long long bm = (long long)blockIdx.x * 128;

    #pragma unroll
    for (int it=0; it<8; it++){
        int idx = tid + it*256;
        int r = idx >> 4, c = idx & 15;
        *(uint4*)&As[r*ASTR + c*8] = *(const uint4*)&hA[(bm+r)*128 + c*8];
    }
    loadW16(Ws, W, tid);
    __syncthreads();

    float acc[4][4][4];
    #pragma unroll
    for (int mi=0;mi<4;mi++)
        #pragma unroll
        for (int ni=0;ni<4;ni++)
            #pragma unroll
            for (int q=0;q<4;q++) acc[mi][ni][q] = 0.0f;
    #pragma unroll
    for (int kk=0; kk<128; kk+=16){
        unsigned af[4][4], bf[4][2];
        loadA(af, As, wm, g, tg, kk);
        loadB(bf, Ws, wn, g, tg, kk);
        #pragma unroll
        for (int mi=0;mi<4;mi++)
            #pragma unroll
            for (int ni=0;ni<4;ni++) mma16816(acc[mi][ni], af[mi], bf[ni]);
    }
    __syncthreads();   // done reading As/Ws; safe to alias Vs

    #pragma unroll
    for (int mi=0;mi<4;mi++){
        int rl = wm + mi*16 + g;
        long long gr = bm + rl;
        float cp0 = cape[gr], cp1 = cape[gr+8];
        #pragma unroll
        for (int ni=0;ni<4;ni++){
            int c0 = wn + ni*8 + 2*tg;
            float b0 = bias[c0], b1 = bias[c0+1];
            float2 q0 = *(const float2*)&Qres[gr*128 + c0];
            float2 q1 = *(const float2*)&Qres[(gr+8)*128 + c0];
            Vs[rl*132 + c0]       = acc[mi][ni][0] + b0 + q0.x + cp0;
            Vs[rl*132 + c0 + 1]   = acc[mi][ni][1] + b1 + q0.y + cp0;
            Vs[(rl+8)*132 + c0]   = acc[mi][ni][2] + b0 + q1.x + cp1;
            Vs[(rl+8)*132 + c0+1] = acc[mi][ni][3] + b1 + q1.y + cp1;
        }
    }
    __syncthreads();

    float4 sv = *(const float4*)&ls[lane*4];
    float4 bv = *(const float4*)&lb[lane*4];
    for (int rr=0; rr<16; rr++){
        int r = warp*16 + rr;
        long long gr = bm + r;
        float4 x = *(const float4*)&Vs[r*132 + lane*4];
        float mean = warpSum(x.x+x.y+x.z+x.w) * (1.0f/D);
        float cx=x.x-mean, cy=x.y-mean, cz=x.z-mean, cw=x.w-mean;
        float var = warpSum(cx*cx+cy*cy+cz*cz+cw*cw) * (1.0f/D);
        float rstd = rsqrtf(var + 1e-8f);
        float o0 = cx*rstd*sv.x+bv.x, o1 = cy*rstd*sv.y+bv.y;
        float o2 = cz*rstd*sv.z+bv.z, o3 = cw*rstd*sv.w+bv.w;
        *(float4*)&s2[gr*128 + lane*4] = make_float4(o0,o1,o2,o3);
        __half2* hp = (__half2*)&hs2[gr*128 + lane*4];
        hp[0] = __floats2half2_rn(o0,o1);
        hp[1] = __floats2half2_rn(o2,o3);
    }
}

// ---------------- fused FFN: out = resid + relu(A@W1^T+b1)@W2^T + b2 -------
__global__ void __launch_bounds__(256, 2)
k_ffn(const __half* __restrict__ hA, const float* __restrict__ resid,
      const __half* __restrict__ W1, const float* __restrict__ b1,
      const __half* __restrict__ W2, const float* __restrict__ b2,
      float* __restrict__ outF, __half* __restrict__ outH)
{
    extern __shared__ __half sm[];
    __half* As = sm;
    __half* Ws = sm + 128*ASTR;
    __half* Hs = As;     // alias after MMA1
    int tid = threadIdx.x;
    int warp = tid >> 5, lane = tid & 31;
    int wm = (warp >> 2) * 64, wn = (warp & 3) * 32;
    int g = lane >> 2, tg = lane & 3;
    long long bm = (long long)blockIdx.x * 128;

    #pragma unroll
    for (int it=0; it<8; it++){
        int idx = tid + it*256;
        int r = idx >> 4, c = idx & 15;
        *(uint4*)&As[r*ASTR + c*8] = *(const uint4*)&hA[(bm+r)*128 + c*8];
    }
    loadW16(Ws, W1, tid);
    __syncthreads();

    float acc[4][4][4];
    #pragma unroll
    for (int mi=0;mi<4;mi++)
        #pragma unroll
        for (int ni=0;ni<4;ni++)
            #pragma unroll
            for (int q=0;q<4;q++) acc[mi][ni][q] = 0.0f;
    #pragma unroll
    for (int kk=0; kk<128; kk+=16){
        unsigned af[4][4], bf[4][2];
        loadA(af, As, wm, g, tg, kk);
        loadB(bf, Ws, wn, g, tg, kk);
        #pragma unroll
        for (int mi=0;mi<4;mi++)
            #pragma unroll
            for (int ni=0;ni<4;ni++) mma16816(acc[mi][ni], af[mi], bf[ni]);
    }
    __syncthreads();   // MMA1 done

    #pragma unroll
    for (int mi=0;mi<4;mi++){
        int rl = wm + mi*16 + g;
        #pragma unroll
        for (int ni=0;ni<4;ni++){
            int c0 = wn + ni*8 + 2*tg;
            float b0 = b1[c0], bb1 = b1[c0+1];
            float h0 = fmaxf(acc[mi][ni][0]+b0, 0.0f);
            float h1 = fmaxf(acc[mi][ni][1]+bb1, 0.0f);
            float h2 = fmaxf(acc[mi][ni][2]+b0, 0.0f);
            float h3 = fmaxf(acc[mi][ni][3]+bb1, 0.0f);
            *(__half2*)&Hs[rl*ASTR + c0]     = __floats2half2_rn(h0, h1);
            *(__half2*)&Hs[(rl+8)*ASTR + c0] = __floats2half2_rn(h2, h3);
        }
    }
    loadW16(Ws, W2, tid);
    __syncthreads();

    #pragma unroll
    for (int mi=0;mi<4;mi++)
        #pragma unroll
        for (int ni=0;ni<4;ni++)
            #pragma unroll
            for (int q=0;q<4;q++) acc[mi][ni][q] = 0.0f;
    #pragma unroll
    for (int kk=0; kk<128; kk+=16){
        unsigned af[4][4], bf[4][2];
        loadA(af, Hs, wm, g, tg, kk);
        loadB(bf, Ws, wn, g, tg, kk);
        #pragma unroll
        for (int mi=0;mi<4;mi++)
            #pragma unroll
            for (int ni=0;ni<4;ni++) mma16816(acc[mi][ni], af[mi], bf[ni]);
    }

    #pragma unroll
    for (int mi=0;mi<4;mi++){
        int rl = wm + mi*16 + g;
        long long gr = bm + rl;
        #pragma unroll
        for (int ni=0;ni<4;ni++){
            int c0 = wn + ni*8 + 2*tg;
            float b0 = b2[c0], bb1 = b2[c0+1];
            float2 r0v = *(const float2*)&resid[gr*128 + c0];
            float2 r1v = *(const float2*)&resid[(gr+8)*128 + c0];
            float v0 = acc[mi][ni][0]+b0+r0v.x, v1 = acc[mi][ni][1]+bb1+r0v.y;
            float v2 = acc[mi][ni][2]+b0+r1v.x, v3 = acc[mi][ni][3]+bb1+r1v.y;
            *(float2*)&outF[gr*128 + c0]     = make_float2(v0, v1);
            *(float2*)&outF[(gr+8)*128 + c0] = make_float2(v2, v3);
            *(__half2*)&outH[gr*128 + c0]     = __floats2half2_rn(v0, v1);
            *(__half2*)&outH[(gr+8)*128 + c0] = __floats2half2_rn(v2, v3);
        }
    }
}

// ---------------- softmax + CAPE, warp per row, chunk-strided ----------------
__global__ void k_softmax_cape2(const __half* __restrict__ scores, const __half* __restrict__ hE,
                                __half* __restrict__ hattn, float* __restrict__ cape)
{
    int warp = threadIdx.x >> 5, lane = threadIdx.x & 31;
    long long row = (long long)blockIdx.x * 8 + warp;
    int qi = (int)(row & (L-1));
    __shared__ __half smE[8][L];
    {
        uint4* dst = (uint4*)&smE[warp][0];
        const uint4* src = (const uint4*)(hE + row*L);
        dst[lane] = src[lane];
        dst[lane+32] = src[lane+32];
    }
    __syncwarp();

    const __half* Sr = scores + row*L;
    __half* Ar = hattn + row*L;
    int nch = qi >> 5;

    float sv[16];
    float m = -3.0e38f;
    #pragma unroll
    for (int j=0;j<16;j++){
        if (j <= nch){
            int k = j*32 + lane;
            float x = __half2float(Sr[k]);
            sv[j] = (k <= qi) ? x : -3.0e38f;
            m = fmaxf(m, sv[j]);
        } else sv[j] = -3.0e38f;
    }
    m = warpMax(m);

    float zs = 0.0f;
    #pragma unroll
    for (int j=0;j<16;j++){
        if (j <= nch){
            float t = (sv[j] > -1.0e37f) ? __expf(sv[j]-m) : 0.0f;
            sv[j] = t; zs += t;
        } else sv[j] = 0.0f;
    }
    float Z = warpSum(zs);
    float invZ = 1.0f / Z;

    float intra[16], ctot[16];
    #pragma unroll
    for (int j=0;j<16;j++){
        int k = j*32 + lane;
        if (j <= nch){
            float a = sv[j]*invZ;
            Ar[k] = __float2half(a);
            float G;
            if (k <= qi){
                float t = __expf(-a);
                G = __fdividef(t, 1.0f + t);
            } else G = 0.5f;
            float v = G;
            #pragma unroll
            for (int off=1; off<32; off<<=1){
                float tt = __shfl_down_sync(0xffffffffu, v, off);
                if (lane + off < 32) v += tt;
            }
            intra[j] = v;
            ctot[j] = __shfl_sync(0xffffffffu, v, 0);
        } else {
            Ar[k] = __float2half(0.0f);
            intra[j] = 0.5f * (32 - lane);
            ctot[j] = 16.0f;
        }
    }

    float running = 0.0f, cv = 0.0f;
    #pragma unroll
    for (int j=15;j>=0;j--){
        float P = intra[j] + running;
        running += ctot[j];
        P = fminf(P, (float)(L-1));
        float Pf = floorf(P);
        float frac = P - Pf;
        int i0 = (int)Pf;
        int i1 = (int)ceilf(P);
        cv += frac*__half2float(smE[warp][i1]) + (1.0f-frac)*__half2float(smE[warp][i0]);
    }
    cv = warpSum(cv);
    if (lane==0) cape[row] = cv * (1.0f/L);
}

// ---------------- host orchestration ----------------
extern "C" void kernel_launch(void* const* d_in, const int* in_sizes, int n_in,
                              void* d_out, int out_size)
{
    const float* item_emb = (const float*)d_in[0];
    const float* pos_emb  = (const float*)d_in[1];
    const float* pre_w    = (const float*)d_in[2];
    const float* pre_b    = (const float*)d_in[3];
    const float* ln1_s    = (const float*)d_in[4];
    const float* ln1_b    = (const float*)d_in[5];
    const float* in_w     = (const float*)d_in[6];
    const float* in_b     = (const float*)d_in[7];
    const float* out_w    = (const float*)d_in[8];
    const float* out_b    = (const float*)d_in[9];
    const float* ln2_s    = (const float*)d_in[10];
    const float* ln2_b    = (const float*)d_in[11];
    const float* c1_w     = (const float*)d_in[12];
    const float* c1_b     = (const float*)d_in[13];
    const float* c2_w     = (const float*)d_in[14];
    const float* c2_b     = (const float*)d_in[15];
    const float* lnf_s    = (const float*)d_in[16];
    const float* lnf_b    = (const float*)d_in[17];
    const int* log_seqs   = (const int*)d_in[19];
    const int* pos_seqs   = (const int*)d_in[20];
    const int* neg_seqs   = (const int*)d_in[21];
    float* out = (float*)d_out;

    float *seqs,*Q,*s2,*cape;
    __half *hseqs,*hQ,*hs2,*hq,*hk,*hv,*hqp,*hmha,*hscores,*hattn,*hE,*hpos,*hw;
    cudaGetSymbolAddress((void**)&seqs,   g_seqs);
    cudaGetSymbolAddress((void**)&Q,      g_Q);
    cudaGetSymbolAddress((void**)&s2,     g_s2);
    cudaGetSymbolAddress((void**)&cape,   g_cape);
    cudaGetSymbolAddress((void**)&hseqs,  g_hseqs);
    cudaGetSymbolAddress((void**)&hQ,     g_hQ);
    cudaGetSymbolAddress((void**)&hs2,    g_hs2);
    cudaGetSymbolAddress((void**)&hq,     g_hq);
    cudaGetSymbolAddress((void**)&hk,     g_hk);
    cudaGetSymbolAddress((void**)&hv,     g_hv);
    cudaGetSymbolAddress((void**)&hqp,    g_hqp);
    cudaGetSymbolAddress((void**)&hmha,   g_hmha);
    cudaGetSymbolAddress((void**)&hscores,g_hscores);
    cudaGetSymbolAddress((void**)&hattn,  g_hattn);
    cudaGetSymbolAddress((void**)&hE,     g_hE);
    cudaGetSymbolAddress((void**)&hpos,   g_hpos);
    cudaGetSymbolAddress((void**)&hw,     g_hw);

    // fp16 weight layout inside g_hw
    __half* hw_in  = hw;                       // 6*D*D
    __half* hw_pre = hw + 6*(size_t)D*D;       // 1
    __half* hw_out = hw + 7*(size_t)D*D;       // 2
    __half* hw_c1  = hw + 9*(size_t)D*D;       // 2
    __half* hw_c2  = hw + 11*(size_t)D*D;      // 2

    cudaFuncSetAttribute(k_qkvp2,    cudaFuncAttributeMaxDynamicSharedMemorySize, 2*TILE_B);
    cudaFuncSetAttribute(k_hgemm128, cudaFuncAttributeMaxDynamicSharedMemorySize, 2*TILE_B);
    cudaFuncSetAttribute(k_oproj_ln, cudaFuncAttributeMaxDynamicSharedMemorySize, 2*TILE_B);
    cudaFuncSetAttribute(k_ffn,      cudaFuncAttributeMaxDynamicSharedMemorySize, 2*TILE_B);

    const float inv_sqrt_d = 1.0f / sqrtf((float)D);

    // one-time (per launch) conversions
    k_f2h<<<(6*D*D+255)/256, 256>>>(in_w,  hw_in,  6*D*D);
    k_f2h<<<(D*D+255)/256,   256>>>(pre_w, hw_pre, D*D);
    k_f2h<<<(2*D*D+255)/256, 256>>>(out_w, hw_out, 2*D*D);
    k_f2h<<<(2*D*D+255)/256, 256>>>(c1_w,  hw_c1,  2*D*D);
    k_f2h<<<(2*D*D+255)/256, 256>>>(c2_w,  hw_c2,  2*D*D);
    k_f2h<<<(D*L+255)/256,   256>>>(pos_emb, hpos, D*L);
    k_embed<<<BL/8, 256>>>(item_emb, log_seqs, seqs, hseqs, sqrtf((float)D));

    for (int i = 0; i < NBLK; i++){
        const float* bq = in_b + (long long)i*3*D;

        k_ln_dual<<<BL/8, 256>>>(seqs, Q, hQ, ln1_s + i*D, ln1_b + i*D);
        k_qkvp2<<<dim3(BL/128, 4), 256, 2*TILE_B>>>(
            hQ, hseqs, hw_in + (long long)i*3*D*D, hw_pre, bq, pre_b,
            hq, hk, hv, hqp);
        k_hgemm128<<<dim3(L/128, L/128, Bb), 256, 2*TILE_B>>>(
            hq, hk, 0, hscores, L,
            (long long)L*D, (long long)L*D, (long long)L*L, inv_sqrt_d, 1, 1);
        k_hgemm128<<<dim3(L/128, BL/128, 1), 256, 2*TILE_B>>>(
            hqp, hpos, 0, hE, L, 0, 0, 0, 1.0f, 0, 0);
        k_softmax_cape2<<<BL/8, 256>>>(hscores, hE, hattn, cape);
        k_hgemm<<<dim3(D/128, L/128, Bb), 256>>>(
            hattn, hv, 0, hmha, L, D, L,
            (long long)L*L, (long long)L*D, (long long)L*D, 1.0f, 0, 2);
        k_oproj_ln<<<BL/128, 256, 2*TILE_B>>>(
            hmha, hw_out + (long long)i*D*D, out_b + i*D, Q, cape,
            ln2_s + i*D, ln2_b + i*D, s2, hs2);
        k_ffn<<<BL/128, 256, 2*TILE_B>>>(
            hs2, s2, hw_c1 + (long long)i*D*D, c1_b + i*D,
            hw_c2 + (long long)i*D*D, c2_b + i*D, seqs, hseqs);
    }

    k_lnlogits<<<BL/8, 256>>>(seqs, lnf_s, lnf_b, item_emb, pos_seqs, neg_seqs, out);
}